// round 8
// baseline (speedup 1.0000x reference)
#include <cuda_runtime.h>
#include <math.h>

#define B_  2
#define S_  2048
#define D_  1024
#define H_  16
#define HD_ 64
#define M_  (B_ * S_)   // 4096

// ---------------- scratch (device globals; no runtime allocation) ----------
__device__ float g_q[(size_t)B_ * H_ * S_ * HD_];     // [B,H,S,hd]
__device__ float g_k[(size_t)B_ * H_ * S_ * HD_];
__device__ float g_v[(size_t)B_ * H_ * S_ * HD_];
__device__ float g_attn[(size_t)M_ * D_];             // [B,S,H,hd] == [B,S,D]

// ---------------------------------------------------------------------------
// 128x128x16 SGEMM, 256 threads, 8x8 register tile, DOUBLE-BUFFERED smem.
// MODE 0: A = x param, W/bias chosen by blockIdx.z in {wq,wk,wv},
//         output permuted into g_q/g_k/g_v as [B,H,S,hd].
// MODE 1: A = g_attn global, W0/bias0 = wo/bo, output linear to Cout.
// ---------------------------------------------------------------------------
template <int MODE>
__global__ void __launch_bounds__(256)
gemm_kernel(const float* __restrict__ A,
            const float* __restrict__ W0, const float* __restrict__ bias0,
            const float* __restrict__ W1, const float* __restrict__ bias1,
            const float* __restrict__ W2, const float* __restrict__ bias2,
            float* __restrict__ Cout)
{
    __shared__ float As[2][16][132];   // [stage][k][m], padded
    __shared__ float Bs[2][16][128];   // [stage][k][n]

    const float* W    = W0;
    const float* bias = bias0;
    float*       dstq = nullptr;
    if (MODE == 0) {
        if (blockIdx.z == 0)      { W = W0; bias = bias0; dstq = g_q; }
        else if (blockIdx.z == 1) { W = W1; bias = bias1; dstq = g_k; }
        else                      { W = W2; bias = bias2; dstq = g_v; }
    }

    const float* Abase = (MODE == 0) ? A : (const float*)g_attn;

    const int tid  = threadIdx.x;
    const int tx   = tid & 15;
    const int ty   = tid >> 4;
    const int arow = tid >> 2;          // 0..63
    const int acol = (tid & 3) << 2;    // 0,4,8,12
    const int brow = tid >> 5;          // 0..7
    const int bcol = (tid & 31) << 2;   // 0..124

    const float* Ap = Abase + (size_t)blockIdx.y * 128 * D_;
    const float* Wp = W + blockIdx.x * 128;

    float acc[8][8];
#pragma unroll
    for (int i = 0; i < 8; i++)
#pragma unroll
        for (int j = 0; j < 8; j++) acc[i][j] = 0.f;

    // ---- prologue: load k-tile 0 into stage 0 ----
    float4 a0 = *(const float4*)(Ap + (size_t)arow        * D_ + acol);
    float4 a1 = *(const float4*)(Ap + (size_t)(arow + 64) * D_ + acol);
    float4 b0 = *(const float4*)(Wp + (size_t)brow       * D_ + bcol);
    float4 b1 = *(const float4*)(Wp + (size_t)(brow + 8) * D_ + bcol);

    As[0][acol + 0][arow] = a0.x; As[0][acol + 1][arow] = a0.y;
    As[0][acol + 2][arow] = a0.z; As[0][acol + 3][arow] = a0.w;
    As[0][acol + 0][arow + 64] = a1.x; As[0][acol + 1][arow + 64] = a1.y;
    As[0][acol + 2][arow + 64] = a1.z; As[0][acol + 3][arow + 64] = a1.w;
    *(float4*)&Bs[0][brow][bcol]     = b0;
    *(float4*)&Bs[0][brow + 8][bcol] = b1;
    __syncthreads();

    const int KT = D_ / 16;   // 64 k-tiles
#pragma unroll 1
    for (int kt = 0; kt < KT; kt++) {
        const int s = kt & 1;

        // issue next tile's LDGs first (latency hidden under compute)
        if (kt + 1 < KT) {
            const int k0 = (kt + 1) * 16;
            a0 = *(const float4*)(Ap + (size_t)arow        * D_ + k0 + acol);
            a1 = *(const float4*)(Ap + (size_t)(arow + 64) * D_ + k0 + acol);
            b0 = *(const float4*)(Wp + (size_t)(k0 + brow)     * D_ + bcol);
            b1 = *(const float4*)(Wp + (size_t)(k0 + brow + 8) * D_ + bcol);
        }

        // compute on stage s
#pragma unroll
        for (int kk = 0; kk < 16; kk++) {
            float rm[8], rn[8];
            *(float4*)&rm[0] = *(const float4*)&As[s][kk][ty * 8];
            *(float4*)&rm[4] = *(const float4*)&As[s][kk][ty * 8 + 4];
            *(float4*)&rn[0] = *(const float4*)&Bs[s][kk][tx * 8];
            *(float4*)&rn[4] = *(const float4*)&Bs[s][kk][tx * 8 + 4];
#pragma unroll
            for (int i = 0; i < 8; i++)
#pragma unroll
                for (int j = 0; j < 8; j++)
                    acc[i][j] += rm[i] * rn[j];
        }

        // store next tile into stage s^1
        if (kt + 1 < KT) {
            const int n = s ^ 1;
            As[n][acol + 0][arow] = a0.x; As[n][acol + 1][arow] = a0.y;
            As[n][acol + 2][arow] = a0.z; As[n][acol + 3][arow] = a0.w;
            As[n][acol + 0][arow + 64] = a1.x; As[n][acol + 1][arow + 64] = a1.y;
            As[n][acol + 2][arow + 64] = a1.z; As[n][acol + 3][arow + 64] = a1.w;
            *(float4*)&Bs[n][brow][bcol]     = b0;
            *(float4*)&Bs[n][brow + 8][bcol] = b1;
        }
        __syncthreads();
    }

    // epilogue: add bias, store
#pragma unroll
    for (int i = 0; i < 8; i++) {
        const int m  = blockIdx.y * 128 + ty * 8 + i;
        const int bb = m / S_;
        const int ss = m % S_;
#pragma unroll
        for (int j = 0; j < 8; j++) {
            const int n = blockIdx.x * 128 + tx * 8 + j;
            const float v = acc[i][j] + bias[n];
            if (MODE == 0) {
                const int h = n >> 6;
                const int d = n & 63;
                dstq[((((size_t)bb * H_ + h) * S_ + ss) << 6) + d] = v;
            } else {
                Cout[(size_t)m * D_ + n] = v;
            }
        }
    }
}

// ---------------------------------------------------------------------------
// Flash attention v2 (causal, fp32): register-tiled micro-GEMMs. (unchanged)
// Block = 128 q rows x one (b,h). KV tile = 64. 256 threads as 16x16.
// ---------------------------------------------------------------------------
#define QS_OFF 0
#define KS_OFF (64 * 132)
#define VS_OFF (KS_OFF + 64 * 68)
#define PS_OFF (VS_OFF + 64 * 68)
#define SMEM_FLOATS (PS_OFF + 128 * 68)

__global__ void __launch_bounds__(256)
attn_kernel()
{
    extern __shared__ float sm[];
    float (*Qs)[132] = (float(*)[132])(sm + QS_OFF);
    float (*Ks)[68]  = (float(*)[68])(sm + KS_OFF);
    float (*Vs)[68]  = (float(*)[68])(sm + VS_OFF);
    float (*Ps)[68]  = (float(*)[68])(sm + PS_OFF);

    const int qt  = blockIdx.x;
    const int bh  = blockIdx.y;
    const int b   = bh >> 4;
    const int h   = bh & 15;
    const int tid = threadIdx.x;
    const int tx  = tid & 15;
    const int ty  = tid >> 4;
    const int q0  = qt * 128;

    const float* Qp = g_q + (size_t)bh * S_ * HD_;
    const float* Kp = g_k + (size_t)bh * S_ * HD_;
    const float* Vp = g_v + (size_t)bh * S_ * HD_;

    // ---- load Q tile transposed (k-major), pre-scaled by 1/sqrt(hd) ----
#pragma unroll
    for (int i = 0; i < 8; i++) {
        const int e  = tid + i * 256;      // 0..2047
        const int r  = e & 127;
        const int k4 = e >> 7;             // 0..15
        float4 qv = *(const float4*)(Qp + (size_t)(q0 + r) * HD_ + k4 * 4);
        Qs[k4 * 4 + 0][r] = qv.x * 0.125f;
        Qs[k4 * 4 + 1][r] = qv.y * 0.125f;
        Qs[k4 * 4 + 2][r] = qv.z * 0.125f;
        Qs[k4 * 4 + 3][r] = qv.w * 0.125f;
    }

    float m_i[8], l_i[8];
    float O[8][4];
#pragma unroll
    for (int i = 0; i < 8; i++) {
        m_i[i] = -1e30f; l_i[i] = 0.f;
#pragma unroll
        for (int j = 0; j < 4; j++) O[i][j] = 0.f;
    }

    const int ntiles = 2 * qt + 2;   // causal
    for (int t = 0; t < ntiles; t++) {
        const int k0 = t * 64;
        __syncthreads();   // prior-tile Ks/Vs/Ps reads complete

        // ---- load K (transposed to k-major) and V (row-major) ----
#pragma unroll
        for (int i = 0; i < 4; i++) {
            const int e  = tid + i * 256;  // 0..1023
            const int c  = e & 63;
            const int k4 = e >> 6;         // 0..15
            float4 kv = *(const float4*)(Kp + (size_t)(k0 + c) * HD_ + k4 * 4);
            Ks[k4 * 4 + 0][c] = kv.x;
            Ks[k4 * 4 + 1][c] = kv.y;
            Ks[k4 * 4 + 2][c] = kv.z;
            Ks[k4 * 4 + 3][c] = kv.w;
            const int vc = e >> 4;         // 0..63
            const int d4 = e & 15;
            float4 vv = *(const float4*)(Vp + (size_t)(k0 + vc) * HD_ + d4 * 4);
            *(float4*)&Vs[vc][d4 * 4] = vv;
        }
        __syncthreads();

        // ---- scores: 8x4 register tile over k = 0..63 ----
        float sc[8][4];
#pragma unroll
        for (int i = 0; i < 8; i++)
#pragma unroll
            for (int j = 0; j < 4; j++) sc[i][j] = 0.f;

#pragma unroll 8
        for (int k = 0; k < 64; k++) {
            float rm[8], rn[4];
            *(float4*)&rm[0] = *(const float4*)&Qs[k][ty * 8];
            *(float4*)&rm[4] = *(const float4*)&Qs[k][ty * 8 + 4];
            *(float4*)&rn[0] = *(const float4*)&Ks[k][tx * 4];
#pragma unroll
            for (int i = 0; i < 8; i++)
#pragma unroll
                for (int j = 0; j < 4; j++)
                    sc[i][j] += rm[i] * rn[j];
        }

        // ---- causal mask (only the last two tiles touch the diagonal) ----
        if (t + 2 >= ntiles) {
#pragma unroll
            for (int i = 0; i < 8; i++) {
                const int qi = q0 + ty * 8 + i;
#pragma unroll
                for (int j = 0; j < 4; j++)
                    if (k0 + tx * 4 + j > qi) sc[i][j] = -1e30f;
            }
        }

        // ---- online softmax: row reductions across the 16 tx lanes ----
        float mx[8];
#pragma unroll
        for (int i = 0; i < 8; i++) {
            float v = fmaxf(fmaxf(sc[i][0], sc[i][1]), fmaxf(sc[i][2], sc[i][3]));
            v = fmaxf(v, __shfl_xor_sync(0xffffffffu, v, 1));
            v = fmaxf(v, __shfl_xor_sync(0xffffffffu, v, 2));
            v = fmaxf(v, __shfl_xor_sync(0xffffffffu, v, 4));
            v = fmaxf(v, __shfl_xor_sync(0xffffffffu, v, 8));
            mx[i] = v;
        }
#pragma unroll
        for (int i = 0; i < 8; i++) {
            const float m_new = fmaxf(m_i[i], mx[i]);
            const float alpha = __expf(m_i[i] - m_new);
            float p0 = __expf(sc[i][0] - m_new);
            float p1 = __expf(sc[i][1] - m_new);
            float p2 = __expf(sc[i][2] - m_new);
            float p3 = __expf(sc[i][3] - m_new);
            *(float4*)&Ps[ty * 8 + i][tx * 4] = make_float4(p0, p1, p2, p3);
            float ls = (p0 + p1) + (p2 + p3);
            ls += __shfl_xor_sync(0xffffffffu, ls, 1);
            ls += __shfl_xor_sync(0xffffffffu, ls, 2);
            ls += __shfl_xor_sync(0xffffffffu, ls, 4);
            ls += __shfl_xor_sync(0xffffffffu, ls, 8);
            l_i[i] = l_i[i] * alpha + ls;
            m_i[i] = m_new;
            O[i][0] *= alpha; O[i][1] *= alpha;
            O[i][2] *= alpha; O[i][3] *= alpha;
        }
        __syncthreads();   // Ps complete before cross-warp PV reads

        // ---- O += P @ V : 8x4 register tile, 4 kv columns per step ----
#pragma unroll 1
        for (int c4 = 0; c4 < 16; c4++) {
            const int c = c4 * 4;
            float v0[4], v1[4], v2[4], v3[4];
            *(float4*)&v0[0] = *(const float4*)&Vs[c + 0][tx * 4];
            *(float4*)&v1[0] = *(const float4*)&Vs[c + 1][tx * 4];
            *(float4*)&v2[0] = *(const float4*)&Vs[c + 2][tx * 4];
            *(float4*)&v3[0] = *(const float4*)&Vs[c + 3][tx * 4];
#pragma unroll
            for (int i = 0; i < 8; i++) {
                float4 pm = *(const float4*)&Ps[ty * 8 + i][c];
#pragma unroll
                for (int j = 0; j < 4; j++)
                    O[i][j] += pm.x * v0[j] + pm.y * v1[j] + pm.z * v2[j] + pm.w * v3[j];
            }
        }
    }

    // ---- finalize: divide by l, write to [B,S,H,hd] (== [B,S,D]) ----
#pragma unroll
    for (int i = 0; i < 8; i++) {
        const float inv = 1.f / l_i[i];
        const int qi = q0 + ty * 8 + i;
        float4 o;
        o.x = O[i][0] * inv; o.y = O[i][1] * inv;
        o.z = O[i][2] * inv; o.w = O[i][3] * inv;
        *(float4*)(g_attn + ((size_t)(b * S_ + qi)) * D_ + h * HD_ + tx * 4) = o;
    }
}

// ---------------------------------------------------------------------------
extern "C" void kernel_launch(void* const* d_in, const int* in_sizes, int n_in,
                              void* d_out, int out_size)
{
    const float* x  = (const float*)d_in[0];
    const float* wq = (const float*)d_in[1];
    const float* bq = (const float*)d_in[2];
    const float* wk = (const float*)d_in[3];
    const float* bk = (const float*)d_in[4];
    const float* wv = (const float*)d_in[5];
    const float* bv = (const float*)d_in[6];
    const float* wo = (const float*)d_in[7];
    const float* bo = (const float*)d_in[8];
    float* out = (float*)d_out;

    // Not a stream op; safe during capture, deterministic on every call.
    cudaFuncSetAttribute(attn_kernel,
                         cudaFuncAttributeMaxDynamicSharedMemorySize,
                         SMEM_FLOATS * (int)sizeof(float));

    // 1) fused QKV projections -> g_q/g_k/g_v in [B,H,S,hd]
    dim3 gq(D_ / 128, M_ / 128, 3);
    gemm_kernel<0><<<gq, 256>>>(x, wq, bq, wk, bk, wv, bv, nullptr);

    // 2) causal flash attention -> g_attn in [B,S,D]
    dim3 ga(S_ / 128, B_ * H_);
    attn_kernel<<<ga, 256, SMEM_FLOATS * (int)sizeof(float)>>>();

    // 3) output projection -> d_out
    dim3 go(D_ / 128, M_ / 128, 1);
    gemm_kernel<1><<<go, 256>>>(nullptr, wo, bo, nullptr, nullptr, nullptr, nullptr, out);
}

// round 9
// speedup vs baseline: 1.1103x; 1.1103x over previous
#include <cuda_runtime.h>
#include <math.h>

#define B_  2
#define S_  2048
#define D_  1024
#define H_  16
#define HD_ 64
#define M_  (B_ * S_)   // 4096

// ---------------- scratch (device globals; no runtime allocation) ----------
__device__ float g_q[(size_t)B_ * H_ * S_ * HD_];     // [B,H,S,hd]
__device__ float g_k[(size_t)B_ * H_ * S_ * HD_];
__device__ float g_v[(size_t)B_ * H_ * S_ * HD_];
__device__ float g_attn[(size_t)M_ * D_];             // [B,S,H,hd] == [B,S,D]

// ---------------------------------------------------------------------------
// 128x128x16 SGEMM, 256 threads, 8x8 register tile, double-buffered smem,
// REGS CAPPED to keep 2 CTAs/SM (the R8 regression: 166 regs -> 1 CTA/SM).
// ---------------------------------------------------------------------------
template <int MODE>
__global__ void __launch_bounds__(256, 2)
gemm_kernel(const float* __restrict__ A,
            const float* __restrict__ W0, const float* __restrict__ bias0,
            const float* __restrict__ W1, const float* __restrict__ bias1,
            const float* __restrict__ W2, const float* __restrict__ bias2,
            float* __restrict__ Cout)
{
    __shared__ float As[2][16][132];   // [stage][k][m], padded
    __shared__ float Bs[2][16][128];   // [stage][k][n]

    const float* W    = W0;
    const float* bias = bias0;
    float*       dstq = nullptr;
    if (MODE == 0) {
        if (blockIdx.z == 0)      { W = W0; bias = bias0; dstq = g_q; }
        else if (blockIdx.z == 1) { W = W1; bias = bias1; dstq = g_k; }
        else                      { W = W2; bias = bias2; dstq = g_v; }
    }

    const float* Abase = (MODE == 0) ? A : (const float*)g_attn;

    const int tid  = threadIdx.x;
    const int tx   = tid & 15;
    const int ty   = tid >> 4;
    const int arow = tid >> 2;          // 0..63
    const int acol = (tid & 3) << 2;    // 0,4,8,12
    const int brow = tid >> 5;          // 0..7
    const int bcol = (tid & 31) << 2;   // 0..124

    // incremented pointers (reduce per-iter IMAD + live regs)
    const float* pA0 = Abase + (size_t)blockIdx.y * 128 * D_ + (size_t)arow * D_ + acol;
    const float* pA1 = pA0 + 64 * D_;
    const float* pB0 = W + blockIdx.x * 128 + (size_t)brow * D_ + bcol;
    const float* pB1 = pB0 + 8 * D_;

    float acc[8][8];
#pragma unroll
    for (int i = 0; i < 8; i++)
#pragma unroll
        for (int j = 0; j < 8; j++) acc[i][j] = 0.f;

    // ---- prologue: load k-tile 0 into stage 0 ----
    float4 a0 = *(const float4*)pA0;
    float4 a1 = *(const float4*)pA1;
    float4 b0 = *(const float4*)pB0;
    float4 b1 = *(const float4*)pB1;
    pA0 += 16; pA1 += 16; pB0 += 16 * D_; pB1 += 16 * D_;

    As[0][acol + 0][arow] = a0.x; As[0][acol + 1][arow] = a0.y;
    As[0][acol + 2][arow] = a0.z; As[0][acol + 3][arow] = a0.w;
    As[0][acol + 0][arow + 64] = a1.x; As[0][acol + 1][arow + 64] = a1.y;
    As[0][acol + 2][arow + 64] = a1.z; As[0][acol + 3][arow + 64] = a1.w;
    *(float4*)&Bs[0][brow][bcol]     = b0;
    *(float4*)&Bs[0][brow + 8][bcol] = b1;
    __syncthreads();

    const int KT = D_ / 16;   // 64 k-tiles
#pragma unroll 1
    for (int kt = 0; kt < KT; kt++) {
        const int s = kt & 1;

        // issue next tile's LDGs first (latency hidden under compute)
        if (kt + 1 < KT) {
            a0 = *(const float4*)pA0;
            a1 = *(const float4*)pA1;
            b0 = *(const float4*)pB0;
            b1 = *(const float4*)pB1;
            pA0 += 16; pA1 += 16; pB0 += 16 * D_; pB1 += 16 * D_;
        }

        // compute on stage s
#pragma unroll
        for (int kk = 0; kk < 16; kk++) {
            float rm[8], rn[8];
            *(float4*)&rm[0] = *(const float4*)&As[s][kk][ty * 8];
            *(float4*)&rm[4] = *(const float4*)&As[s][kk][ty * 8 + 4];
            *(float4*)&rn[0] = *(const float4*)&Bs[s][kk][tx * 8];
            *(float4*)&rn[4] = *(const float4*)&Bs[s][kk][tx * 8 + 4];
#pragma unroll
            for (int i = 0; i < 8; i++)
#pragma unroll
                for (int j = 0; j < 8; j++)
                    acc[i][j] += rm[i] * rn[j];
        }

        // store next tile into stage s^1
        if (kt + 1 < KT) {
            const int n = s ^ 1;
            As[n][acol + 0][arow] = a0.x; As[n][acol + 1][arow] = a0.y;
            As[n][acol + 2][arow] = a0.z; As[n][acol + 3][arow] = a0.w;
            As[n][acol + 0][arow + 64] = a1.x; As[n][acol + 1][arow + 64] = a1.y;
            As[n][acol + 2][arow + 64] = a1.z; As[n][acol + 3][arow + 64] = a1.w;
            *(float4*)&Bs[n][brow][bcol]     = b0;
            *(float4*)&Bs[n][brow + 8][bcol] = b1;
        }
        __syncthreads();
    }

    // epilogue: add bias, store
#pragma unroll
    for (int i = 0; i < 8; i++) {
        const int m  = blockIdx.y * 128 + ty * 8 + i;
        const int bb = m / S_;
        const int ss = m % S_;
#pragma unroll
        for (int j = 0; j < 8; j++) {
            const int n = blockIdx.x * 128 + tx * 8 + j;
            const float v = acc[i][j] + bias[n];
            if (MODE == 0) {
                const int h = n >> 6;
                const int d = n & 63;
                dstq[((((size_t)bb * H_ + h) * S_ + ss) << 6) + d] = v;
            } else {
                Cout[(size_t)m * D_ + n] = v;
            }
        }
    }
}

// ---------------------------------------------------------------------------
// Flash attention v2 (causal, fp32): register-tiled micro-GEMMs. (unchanged)
// Block = 128 q rows x one (b,h). KV tile = 64. 256 threads as 16x16.
// ---------------------------------------------------------------------------
#define QS_OFF 0
#define KS_OFF (64 * 132)
#define VS_OFF (KS_OFF + 64 * 68)
#define PS_OFF (VS_OFF + 64 * 68)
#define SMEM_FLOATS (PS_OFF + 128 * 68)

__global__ void __launch_bounds__(256)
attn_kernel()
{
    extern __shared__ float sm[];
    float (*Qs)[132] = (float(*)[132])(sm + QS_OFF);
    float (*Ks)[68]  = (float(*)[68])(sm + KS_OFF);
    float (*Vs)[68]  = (float(*)[68])(sm + VS_OFF);
    float (*Ps)[68]  = (float(*)[68])(sm + PS_OFF);

    const int qt  = blockIdx.x;
    const int bh  = blockIdx.y;
    const int b   = bh >> 4;
    const int h   = bh & 15;
    const int tid = threadIdx.x;
    const int tx  = tid & 15;
    const int ty  = tid >> 4;
    const int q0  = qt * 128;

    const float* Qp = g_q + (size_t)bh * S_ * HD_;
    const float* Kp = g_k + (size_t)bh * S_ * HD_;
    const float* Vp = g_v + (size_t)bh * S_ * HD_;

    // ---- load Q tile transposed (k-major), pre-scaled by 1/sqrt(hd) ----
#pragma unroll
    for (int i = 0; i < 8; i++) {
        const int e  = tid + i * 256;      // 0..2047
        const int r  = e & 127;
        const int k4 = e >> 7;             // 0..15
        float4 qv = *(const float4*)(Qp + (size_t)(q0 + r) * HD_ + k4 * 4);
        Qs[k4 * 4 + 0][r] = qv.x * 0.125f;
        Qs[k4 * 4 + 1][r] = qv.y * 0.125f;
        Qs[k4 * 4 + 2][r] = qv.z * 0.125f;
        Qs[k4 * 4 + 3][r] = qv.w * 0.125f;
    }

    float m_i[8], l_i[8];
    float O[8][4];
#pragma unroll
    for (int i = 0; i < 8; i++) {
        m_i[i] = -1e30f; l_i[i] = 0.f;
#pragma unroll
        for (int j = 0; j < 4; j++) O[i][j] = 0.f;
    }

    const int ntiles = 2 * qt + 2;   // causal
    for (int t = 0; t < ntiles; t++) {
        const int k0 = t * 64;
        __syncthreads();   // prior-tile Ks/Vs/Ps reads complete

        // ---- load K (transposed to k-major) and V (row-major) ----
#pragma unroll
        for (int i = 0; i < 4; i++) {
            const int e  = tid + i * 256;  // 0..1023
            const int c  = e & 63;
            const int k4 = e >> 6;         // 0..15
            float4 kv = *(const float4*)(Kp + (size_t)(k0 + c) * HD_ + k4 * 4);
            Ks[k4 * 4 + 0][c] = kv.x;
            Ks[k4 * 4 + 1][c] = kv.y;
            Ks[k4 * 4 + 2][c] = kv.z;
            Ks[k4 * 4 + 3][c] = kv.w;
            const int vc = e >> 4;         // 0..63
            const int d4 = e & 15;
            float4 vv = *(const float4*)(Vp + (size_t)(k0 + vc) * HD_ + d4 * 4);
            *(float4*)&Vs[vc][d4 * 4] = vv;
        }
        __syncthreads();

        // ---- scores: 8x4 register tile over k = 0..63 ----
        float sc[8][4];
#pragma unroll
        for (int i = 0; i < 8; i++)
#pragma unroll
            for (int j = 0; j < 4; j++) sc[i][j] = 0.f;

#pragma unroll 8
        for (int k = 0; k < 64; k++) {
            float rm[8], rn[4];
            *(float4*)&rm[0] = *(const float4*)&Qs[k][ty * 8];
            *(float4*)&rm[4] = *(const float4*)&Qs[k][ty * 8 + 4];
            *(float4*)&rn[0] = *(const float4*)&Ks[k][tx * 4];
#pragma unroll
            for (int i = 0; i < 8; i++)
#pragma unroll
                for (int j = 0; j < 4; j++)
                    sc[i][j] += rm[i] * rn[j];
        }

        // ---- causal mask (only the last two tiles touch the diagonal) ----
        if (t + 2 >= ntiles) {
#pragma unroll
            for (int i = 0; i < 8; i++) {
                const int qi = q0 + ty * 8 + i;
#pragma unroll
                for (int j = 0; j < 4; j++)
                    if (k0 + tx * 4 + j > qi) sc[i][j] = -1e30f;
            }
        }

        // ---- online softmax: row reductions across the 16 tx lanes ----
        float mx[8];
#pragma unroll
        for (int i = 0; i < 8; i++) {
            float v = fmaxf(fmaxf(sc[i][0], sc[i][1]), fmaxf(sc[i][2], sc[i][3]));
            v = fmaxf(v, __shfl_xor_sync(0xffffffffu, v, 1));
            v = fmaxf(v, __shfl_xor_sync(0xffffffffu, v, 2));
            v = fmaxf(v, __shfl_xor_sync(0xffffffffu, v, 4));
            v = fmaxf(v, __shfl_xor_sync(0xffffffffu, v, 8));
            mx[i] = v;
        }
#pragma unroll
        for (int i = 0; i < 8; i++) {
            const float m_new = fmaxf(m_i[i], mx[i]);
            const float alpha = __expf(m_i[i] - m_new);
            float p0 = __expf(sc[i][0] - m_new);
            float p1 = __expf(sc[i][1] - m_new);
            float p2 = __expf(sc[i][2] - m_new);
            float p3 = __expf(sc[i][3] - m_new);
            *(float4*)&Ps[ty * 8 + i][tx * 4] = make_float4(p0, p1, p2, p3);
            float ls = (p0 + p1) + (p2 + p3);
            ls += __shfl_xor_sync(0xffffffffu, ls, 1);
            ls += __shfl_xor_sync(0xffffffffu, ls, 2);
            ls += __shfl_xor_sync(0xffffffffu, ls, 4);
            ls += __shfl_xor_sync(0xffffffffu, ls, 8);
            l_i[i] = l_i[i] * alpha + ls;
            m_i[i] = m_new;
            O[i][0] *= alpha; O[i][1] *= alpha;
            O[i][2] *= alpha; O[i][3] *= alpha;
        }
        __syncthreads();   // Ps complete before cross-warp PV reads

        // ---- O += P @ V : 8x4 register tile, 4 kv columns per step ----
#pragma unroll 1
        for (int c4 = 0; c4 < 16; c4++) {
            const int c = c4 * 4;
            float v0[4], v1[4], v2[4], v3[4];
            *(float4*)&v0[0] = *(const float4*)&Vs[c + 0][tx * 4];
            *(float4*)&v1[0] = *(const float4*)&Vs[c + 1][tx * 4];
            *(float4*)&v2[0] = *(const float4*)&Vs[c + 2][tx * 4];
            *(float4*)&v3[0] = *(const float4*)&Vs[c + 3][tx * 4];
#pragma unroll
            for (int i = 0; i < 8; i++) {
                float4 pm = *(const float4*)&Ps[ty * 8 + i][c];
#pragma unroll
                for (int j = 0; j < 4; j++)
                    O[i][j] += pm.x * v0[j] + pm.y * v1[j] + pm.z * v2[j] + pm.w * v3[j];
            }
        }
    }

    // ---- finalize: divide by l, write to [B,S,H,hd] (== [B,S,D]) ----
#pragma unroll
    for (int i = 0; i < 8; i++) {
        const float inv = 1.f / l_i[i];
        const int qi = q0 + ty * 8 + i;
        float4 o;
        o.x = O[i][0] * inv; o.y = O[i][1] * inv;
        o.z = O[i][2] * inv; o.w = O[i][3] * inv;
        *(float4*)(g_attn + ((size_t)(b * S_ + qi)) * D_ + h * HD_ + tx * 4) = o;
    }
}

// ---------------------------------------------------------------------------
extern "C" void kernel_launch(void* const* d_in, const int* in_sizes, int n_in,
                              void* d_out, int out_size)
{
    const float* x  = (const float*)d_in[0];
    const float* wq = (const float*)d_in[1];
    const float* bq = (const float*)d_in[2];
    const float* wk = (const float*)d_in[3];
    const float* bk = (const float*)d_in[4];
    const float* wv = (const float*)d_in[5];
    const float* bv = (const float*)d_in[6];
    const float* wo = (const float*)d_in[7];
    const float* bo = (const float*)d_in[8];
    float* out = (float*)d_out;

    cudaFuncSetAttribute(attn_kernel,
                         cudaFuncAttributeMaxDynamicSharedMemorySize,
                         SMEM_FLOATS * (int)sizeof(float));

    // 1) fused QKV projections -> g_q/g_k/g_v in [B,H,S,hd]
    dim3 gq(D_ / 128, M_ / 128, 3);
    gemm_kernel<0><<<gq, 256>>>(x, wq, bq, wk, bk, wv, bv, nullptr);

    // 2) causal flash attention -> g_attn in [B,S,D]
    dim3 ga(S_ / 128, B_ * H_);
    attn_kernel<<<ga, 256, SMEM_FLOATS * (int)sizeof(float)>>>();

    // 3) output projection -> d_out
    dim3 go(D_ / 128, M_ / 128, 1);
    gemm_kernel<1><<<go, 256>>>(nullptr, wo, bo, nullptr, nullptr, nullptr, nullptr, out);
}

// round 10
// speedup vs baseline: 1.1659x; 1.0502x over previous
#include <cuda_runtime.h>
#include <math.h>

#define B_  2
#define S_  2048
#define D_  1024
#define H_  16
#define HD_ 64
#define M_  (B_ * S_)   // 4096

// ---------------- scratch (device globals; no runtime allocation) ----------
__device__ float g_q[(size_t)B_ * H_ * S_ * HD_];     // [B,H,S,hd]
__device__ float g_k[(size_t)B_ * H_ * S_ * HD_];
__device__ float g_v[(size_t)B_ * H_ * S_ * HD_];
__device__ float g_attn[(size_t)M_ * D_];             // [B,S,H,hd] == [B,S,D]

// ---------------------------------------------------------------------------
// 128x128x16 SGEMM, 256 threads, double-buffered smem, 2 CTAs/SM.
// Fragment-SPLIT 8x8 register tile (rows ty*4/+64, cols tx*4/+64):
// all LDS.128 fragment loads have 16B lane stride -> conflict-free
// (fixes the R9 smem-crossbar bottleneck: L1 was 78.8% vs fma 53.5%).
// ---------------------------------------------------------------------------
template <int MODE>
__global__ void __launch_bounds__(256, 2)
gemm_kernel(const float* __restrict__ A,
            const float* __restrict__ W0, const float* __restrict__ bias0,
            const float* __restrict__ W1, const float* __restrict__ bias1,
            const float* __restrict__ W2, const float* __restrict__ bias2,
            float* __restrict__ Cout)
{
    __shared__ float As[2][16][132];   // [stage][k][m], padded
    __shared__ float Bs[2][16][128];   // [stage][k][n]

    const float* W    = W0;
    const float* bias = bias0;
    float*       dstq = nullptr;
    if (MODE == 0) {
        if (blockIdx.z == 0)      { W = W0; bias = bias0; dstq = g_q; }
        else if (blockIdx.z == 1) { W = W1; bias = bias1; dstq = g_k; }
        else                      { W = W2; bias = bias2; dstq = g_v; }
    }

    const float* Abase = (MODE == 0) ? A : (const float*)g_attn;

    const int tid  = threadIdx.x;
    const int tx   = tid & 15;
    const int ty   = tid >> 4;
    const int arow = tid >> 2;          // 0..63
    const int acol = (tid & 3) << 2;    // 0,4,8,12
    const int brow = tid >> 5;          // 0..7
    const int bcol = (tid & 31) << 2;   // 0..124

    // incremented pointers
    const float* pA0 = Abase + (size_t)blockIdx.y * 128 * D_ + (size_t)arow * D_ + acol;
    const float* pA1 = pA0 + 64 * D_;
    const float* pB0 = W + blockIdx.x * 128 + (size_t)brow * D_ + bcol;
    const float* pB1 = pB0 + 8 * D_;

    float acc[8][8];
#pragma unroll
    for (int i = 0; i < 8; i++)
#pragma unroll
        for (int j = 0; j < 8; j++) acc[i][j] = 0.f;

    // ---- prologue: load k-tile 0 into stage 0 ----
    float4 a0 = *(const float4*)pA0;
    float4 a1 = *(const float4*)pA1;
    float4 b0 = *(const float4*)pB0;
    float4 b1 = *(const float4*)pB1;
    pA0 += 16; pA1 += 16; pB0 += 16 * D_; pB1 += 16 * D_;

    As[0][acol + 0][arow] = a0.x; As[0][acol + 1][arow] = a0.y;
    As[0][acol + 2][arow] = a0.z; As[0][acol + 3][arow] = a0.w;
    As[0][acol + 0][arow + 64] = a1.x; As[0][acol + 1][arow + 64] = a1.y;
    As[0][acol + 2][arow + 64] = a1.z; As[0][acol + 3][arow + 64] = a1.w;
    *(float4*)&Bs[0][brow][bcol]     = b0;
    *(float4*)&Bs[0][brow + 8][bcol] = b1;
    __syncthreads();

    const int KT = D_ / 16;   // 64 k-tiles
#pragma unroll 1
    for (int kt = 0; kt < KT; kt++) {
        const int s = kt & 1;

        // issue next tile's LDGs first (latency hidden under compute)
        if (kt + 1 < KT) {
            a0 = *(const float4*)pA0;
            a1 = *(const float4*)pA1;
            b0 = *(const float4*)pB0;
            b1 = *(const float4*)pB1;
            pA0 += 16; pA1 += 16; pB0 += 16 * D_; pB1 += 16 * D_;
        }

        // compute on stage s — split fragments, conflict-free LDS
#pragma unroll
        for (int kk = 0; kk < 16; kk++) {
            float rm[8], rn[8];
            *(float4*)&rm[0] = *(const float4*)&As[s][kk][ty * 4];
            *(float4*)&rm[4] = *(const float4*)&As[s][kk][64 + ty * 4];
            *(float4*)&rn[0] = *(const float4*)&Bs[s][kk][tx * 4];
            *(float4*)&rn[4] = *(const float4*)&Bs[s][kk][64 + tx * 4];
#pragma unroll
            for (int i = 0; i < 8; i++)
#pragma unroll
                for (int j = 0; j < 8; j++)
                    acc[i][j] += rm[i] * rn[j];
        }

        // store next tile into stage s^1
        if (kt + 1 < KT) {
            const int n = s ^ 1;
            As[n][acol + 0][arow] = a0.x; As[n][acol + 1][arow] = a0.y;
            As[n][acol + 2][arow] = a0.z; As[n][acol + 3][arow] = a0.w;
            As[n][acol + 0][arow + 64] = a1.x; As[n][acol + 1][arow + 64] = a1.y;
            As[n][acol + 2][arow + 64] = a1.z; As[n][acol + 3][arow + 64] = a1.w;
            *(float4*)&Bs[n][brow][bcol]     = b0;
            *(float4*)&Bs[n][brow + 8][bcol] = b1;
        }
        __syncthreads();
    }

    // ---- epilogue: bias + store (float4; 4-col spans stay in one head) ----
#pragma unroll
    for (int ih = 0; ih < 2; ih++) {
#pragma unroll
        for (int ii = 0; ii < 4; ii++) {
            const int i  = ih * 4 + ii;
            const int m  = blockIdx.y * 128 + ih * 64 + ty * 4 + ii;
            const int bb = m / S_;
            const int ss = m % S_;
#pragma unroll
            for (int jh = 0; jh < 2; jh++) {
                const int n0 = blockIdx.x * 128 + jh * 64 + tx * 4;
                float4 bv = *(const float4*)&bias[n0];
                float4 v;
                v.x = acc[i][jh * 4 + 0] + bv.x;
                v.y = acc[i][jh * 4 + 1] + bv.y;
                v.z = acc[i][jh * 4 + 2] + bv.z;
                v.w = acc[i][jh * 4 + 3] + bv.w;
                if (MODE == 0) {
                    const int h = n0 >> 6;
                    const int d = n0 & 63;
                    *(float4*)(dstq + ((((size_t)bb * H_ + h) * S_ + ss) << 6) + d) = v;
                } else {
                    *(float4*)(Cout + (size_t)m * D_ + n0) = v;
                }
            }
        }
    }
}

// ---------------------------------------------------------------------------
// Flash attention v2 (causal, fp32): register-tiled micro-GEMMs. (unchanged)
// ---------------------------------------------------------------------------
#define QS_OFF 0
#define KS_OFF (64 * 132)
#define VS_OFF (KS_OFF + 64 * 68)
#define PS_OFF (VS_OFF + 64 * 68)
#define SMEM_FLOATS (PS_OFF + 128 * 68)

__global__ void __launch_bounds__(256)
attn_kernel()
{
    extern __shared__ float sm[];
    float (*Qs)[132] = (float(*)[132])(sm + QS_OFF);
    float (*Ks)[68]  = (float(*)[68])(sm + KS_OFF);
    float (*Vs)[68]  = (float(*)[68])(sm + VS_OFF);
    float (*Ps)[68]  = (float(*)[68])(sm + PS_OFF);

    const int qt  = blockIdx.x;
    const int bh  = blockIdx.y;
    const int b   = bh >> 4;
    const int h   = bh & 15;
    const int tid = threadIdx.x;
    const int tx  = tid & 15;
    const int ty  = tid >> 4;
    const int q0  = qt * 128;

    const float* Qp = g_q + (size_t)bh * S_ * HD_;
    const float* Kp = g_k + (size_t)bh * S_ * HD_;
    const float* Vp = g_v + (size_t)bh * S_ * HD_;

    // ---- load Q tile transposed (k-major), pre-scaled by 1/sqrt(hd) ----
#pragma unroll
    for (int i = 0; i < 8; i++) {
        const int e  = tid + i * 256;      // 0..2047
        const int r  = e & 127;
        const int k4 = e >> 7;             // 0..15
        float4 qv = *(const float4*)(Qp + (size_t)(q0 + r) * HD_ + k4 * 4);
        Qs[k4 * 4 + 0][r] = qv.x * 0.125f;
        Qs[k4 * 4 + 1][r] = qv.y * 0.125f;
        Qs[k4 * 4 + 2][r] = qv.z * 0.125f;
        Qs[k4 * 4 + 3][r] = qv.w * 0.125f;
    }

    float m_i[8], l_i[8];
    float O[8][4];
#pragma unroll
    for (int i = 0; i < 8; i++) {
        m_i[i] = -1e30f; l_i[i] = 0.f;
#pragma unroll
        for (int j = 0; j < 4; j++) O[i][j] = 0.f;
    }

    const int ntiles = 2 * qt + 2;   // causal
    for (int t = 0; t < ntiles; t++) {
        const int k0 = t * 64;
        __syncthreads();   // prior-tile Ks/Vs/Ps reads complete

        // ---- load K (transposed to k-major) and V (row-major) ----
#pragma unroll
        for (int i = 0; i < 4; i++) {
            const int e  = tid + i * 256;  // 0..1023
            const int c  = e & 63;
            const int k4 = e >> 6;         // 0..15
            float4 kv = *(const float4*)(Kp + (size_t)(k0 + c) * HD_ + k4 * 4);
            Ks[k4 * 4 + 0][c] = kv.x;
            Ks[k4 * 4 + 1][c] = kv.y;
            Ks[k4 * 4 + 2][c] = kv.z;
            Ks[k4 * 4 + 3][c] = kv.w;
            const int vc = e >> 4;         // 0..63
            const int d4 = e & 15;
            float4 vv = *(const float4*)(Vp + (size_t)(k0 + vc) * HD_ + d4 * 4);
            *(float4*)&Vs[vc][d4 * 4] = vv;
        }
        __syncthreads();

        // ---- scores: 8x4 register tile over k = 0..63 ----
        float sc[8][4];
#pragma unroll
        for (int i = 0; i < 8; i++)
#pragma unroll
            for (int j = 0; j < 4; j++) sc[i][j] = 0.f;

#pragma unroll 8
        for (int k = 0; k < 64; k++) {
            float rm[8], rn[4];
            *(float4*)&rm[0] = *(const float4*)&Qs[k][ty * 8];
            *(float4*)&rm[4] = *(const float4*)&Qs[k][ty * 8 + 4];
            *(float4*)&rn[0] = *(const float4*)&Ks[k][tx * 4];
#pragma unroll
            for (int i = 0; i < 8; i++)
#pragma unroll
                for (int j = 0; j < 4; j++)
                    sc[i][j] += rm[i] * rn[j];
        }

        // ---- causal mask (only the last two tiles touch the diagonal) ----
        if (t + 2 >= ntiles) {
#pragma unroll
            for (int i = 0; i < 8; i++) {
                const int qi = q0 + ty * 8 + i;
#pragma unroll
                for (int j = 0; j < 4; j++)
                    if (k0 + tx * 4 + j > qi) sc[i][j] = -1e30f;
            }
        }

        // ---- online softmax: row reductions across the 16 tx lanes ----
        float mx[8];
#pragma unroll
        for (int i = 0; i < 8; i++) {
            float v = fmaxf(fmaxf(sc[i][0], sc[i][1]), fmaxf(sc[i][2], sc[i][3]));
            v = fmaxf(v, __shfl_xor_sync(0xffffffffu, v, 1));
            v = fmaxf(v, __shfl_xor_sync(0xffffffffu, v, 2));
            v = fmaxf(v, __shfl_xor_sync(0xffffffffu, v, 4));
            v = fmaxf(v, __shfl_xor_sync(0xffffffffu, v, 8));
            mx[i] = v;
        }
#pragma unroll
        for (int i = 0; i < 8; i++) {
            const float m_new = fmaxf(m_i[i], mx[i]);
            const float alpha = __expf(m_i[i] - m_new);
            float p0 = __expf(sc[i][0] - m_new);
            float p1 = __expf(sc[i][1] - m_new);
            float p2 = __expf(sc[i][2] - m_new);
            float p3 = __expf(sc[i][3] - m_new);
            *(float4*)&Ps[ty * 8 + i][tx * 4] = make_float4(p0, p1, p2, p3);
            float ls = (p0 + p1) + (p2 + p3);
            ls += __shfl_xor_sync(0xffffffffu, ls, 1);
            ls += __shfl_xor_sync(0xffffffffu, ls, 2);
            ls += __shfl_xor_sync(0xffffffffu, ls, 4);
            ls += __shfl_xor_sync(0xffffffffu, ls, 8);
            l_i[i] = l_i[i] * alpha + ls;
            m_i[i] = m_new;
            O[i][0] *= alpha; O[i][1] *= alpha;
            O[i][2] *= alpha; O[i][3] *= alpha;
        }
        __syncthreads();   // Ps complete before cross-warp PV reads

        // ---- O += P @ V : 8x4 register tile, 4 kv columns per step ----
#pragma unroll 1
        for (int c4 = 0; c4 < 16; c4++) {
            const int c = c4 * 4;
            float v0[4], v1[4], v2[4], v3[4];
            *(float4*)&v0[0] = *(const float4*)&Vs[c + 0][tx * 4];
            *(float4*)&v1[0] = *(const float4*)&Vs[c + 1][tx * 4];
            *(float4*)&v2[0] = *(const float4*)&Vs[c + 2][tx * 4];
            *(float4*)&v3[0] = *(const float4*)&Vs[c + 3][tx * 4];
#pragma unroll
            for (int i = 0; i < 8; i++) {
                float4 pm = *(const float4*)&Ps[ty * 8 + i][c];
#pragma unroll
                for (int j = 0; j < 4; j++)
                    O[i][j] += pm.x * v0[j] + pm.y * v1[j] + pm.z * v2[j] + pm.w * v3[j];
            }
        }
    }

    // ---- finalize: divide by l, write to [B,S,H,hd] (== [B,S,D]) ----
#pragma unroll
    for (int i = 0; i < 8; i++) {
        const float inv = 1.f / l_i[i];
        const int qi = q0 + ty * 8 + i;
        float4 o;
        o.x = O[i][0] * inv; o.y = O[i][1] * inv;
        o.z = O[i][2] * inv; o.w = O[i][3] * inv;
        *(float4*)(g_attn + ((size_t)(b * S_ + qi)) * D_ + h * HD_ + tx * 4) = o;
    }
}

// ---------------------------------------------------------------------------
extern "C" void kernel_launch(void* const* d_in, const int* in_sizes, int n_in,
                              void* d_out, int out_size)
{
    const float* x  = (const float*)d_in[0];
    const float* wq = (const float*)d_in[1];
    const float* bq = (const float*)d_in[2];
    const float* wk = (const float*)d_in[3];
    const float* bk = (const float*)d_in[4];
    const float* wv = (const float*)d_in[5];
    const float* bv = (const float*)d_in[6];
    const float* wo = (const float*)d_in[7];
    const float* bo = (const float*)d_in[8];
    float* out = (float*)d_out;

    cudaFuncSetAttribute(attn_kernel,
                         cudaFuncAttributeMaxDynamicSharedMemorySize,
                         SMEM_FLOATS * (int)sizeof(float));

    // 1) fused QKV projections -> g_q/g_k/g_v in [B,H,S,hd]
    dim3 gq(D_ / 128, M_ / 128, 3);
    gemm_kernel<0><<<gq, 256>>>(x, wq, bq, wk, bk, wv, bv, nullptr);

    // 2) causal flash attention -> g_attn in [B,S,D]
    dim3 ga(S_ / 128, B_ * H_);
    attn_kernel<<<ga, 256, SMEM_FLOATS * (int)sizeof(float)>>>();

    // 3) output projection -> d_out
    dim3 go(D_ / 128, M_ / 128, 1);
    gemm_kernel<1><<<go, 256>>>(nullptr, wo, bo, nullptr, nullptr, nullptr, nullptr, out);
}

// round 12
// speedup vs baseline: 1.7776x; 1.5246x over previous
#include <cuda_runtime.h>
#include <math.h>
#include <stdint.h>

#define B_  2
#define S_  2048
#define D_  1024
#define H_  16
#define HD_ 64
#define M_  (B_ * S_)   // 4096

// ---------------- scratch (device globals; no runtime allocation) ----------
__device__ float g_q[(size_t)B_ * H_ * S_ * HD_];     // [B,H,S,hd]
__device__ float g_k[(size_t)B_ * H_ * S_ * HD_];
__device__ float g_v[(size_t)B_ * H_ * S_ * HD_];
__device__ float g_attn[(size_t)M_ * D_];             // [B,S,H,hd] == [B,S,D]

// ======================= helpers ===========================================
__device__ __forceinline__ uint32_t smem_u32(const void* p) {
    uint32_t a;
    asm("{ .reg .u64 t; cvta.to.shared.u64 t, %1; cvt.u32.u64 %0, t; }"
        : "=r"(a) : "l"(p));
    return a;
}
__device__ __forceinline__ uint32_t f2tf32(float f) {
    uint32_t r;
    asm("cvt.rna.tf32.f32 %0, %1;" : "=r"(r) : "f"(f));
    return r;
}
#define CP_ASYNC16(dst, src) \
    asm volatile("cp.async.cg.shared.global [%0], [%1], 16;" \
                 :: "r"(dst), "l"(src) : "memory")
#define CP_COMMIT() asm volatile("cp.async.commit_group;" ::: "memory")
#define CP_WAIT0()  asm volatile("cp.async.wait_group 0;" ::: "memory")
#define CP_WAIT1()  asm volatile("cp.async.wait_group 1;" ::: "memory")

__device__ __forceinline__ void mma_tf32(float* c, uint32_t a0, uint32_t a1,
                                         uint32_t a2, uint32_t a3,
                                         uint32_t b0, uint32_t b1) {
    asm volatile(
        "mma.sync.aligned.m16n8k8.row.col.f32.tf32.tf32.f32 "
        "{%0,%1,%2,%3}, {%4,%5,%6,%7}, {%8,%9}, {%0,%1,%2,%3};"
        : "+f"(c[0]), "+f"(c[1]), "+f"(c[2]), "+f"(c[3])
        : "r"(a0), "r"(a1), "r"(a2), "r"(a3), "r"(b0), "r"(b1));
}

// ======================= tf32 mma.sync GEMM ================================
// CTA 128x128, 8 warps (2m x 4n), warp tile m64 x n32.
// K chunks of 32, cp.async double-buffered smem.
// As[128][36] (bank 4r+c conflict-free), Bs[32][136] (bank 8k+n conflict-free).
#define GA_STRIDE 36
#define GB_STRIDE 136
#define GA_BYTES (128 * GA_STRIDE * 4)            // 18432
#define GB_BYTES (32 * GB_STRIDE * 4)             // 17408
#define GSTAGE   (GA_BYTES + GB_BYTES)            // 35840
#define GA_OFF(s) ((s) * GSTAGE)
#define GB_OFF(s) ((s) * GSTAGE + GA_BYTES)
#define G_SMEM    (2 * GSTAGE)                    // 71680
#define G_NC      (D_ / 32)                       // 32 chunks

template <int MODE>
__global__ void __launch_bounds__(256)
gemm_tc(const float* __restrict__ A,
        const float* __restrict__ W0, const float* __restrict__ bias0,
        const float* __restrict__ W1, const float* __restrict__ bias1,
        const float* __restrict__ W2, const float* __restrict__ bias2,
        float* __restrict__ Cout)
{
    extern __shared__ char smc[];
    const uint32_t smb = smem_u32(smc);

    const float* W    = W0;
    const float* bias = bias0;
    float*       dstq = nullptr;
    if (MODE == 0) {
        if (blockIdx.z == 0)      { W = W0; bias = bias0; dstq = g_q; }
        else if (blockIdx.z == 1) { W = W1; bias = bias1; dstq = g_k; }
        else                      { W = W2; bias = bias2; dstq = g_v; }
    }
    const float* Ab = (MODE == 0) ? A : (const float*)g_attn;

    const int tid    = threadIdx.x;
    const int lid    = tid & 31;
    const int wid    = tid >> 5;
    const int warp_m = wid >> 2;         // 0..1
    const int warp_n = wid & 3;          // 0..3
    const int g      = lid >> 2;         // 0..7
    const int qq     = lid & 3;          // 0..3
    const int m0     = blockIdx.y * 128;
    const int n0     = blockIdx.x * 128;
    const int rb     = warp_m * 64;
    const int cb     = warp_n * 32;

    float acc[4][4][4];
#pragma unroll
    for (int mt = 0; mt < 4; mt++)
#pragma unroll
        for (int nt = 0; nt < 4; nt++)
#pragma unroll
            for (int e = 0; e < 4; e++) acc[mt][nt][e] = 0.f;

    // ---- chunk loader via cp.async ----
    auto load_chunk = [&](int c, int s) {
        const int k0 = c * 32;
        const uint32_t sa = smb + GA_OFF(s);
        const uint32_t sb = smb + GB_OFF(s);
        // A: 128 rows x 32 k = 1024 float4, 4/thread
#pragma unroll
        for (int i = 0; i < 4; i++) {
            const int e   = tid + i * 256;
            const int row = e >> 3;
            const int c4  = (e & 7) * 4;
            const float* src = Ab + (size_t)(m0 + row) * D_ + k0 + c4;
            CP_ASYNC16(sa + (uint32_t)(row * GA_STRIDE + c4) * 4, src);
        }
        // B (W[k][n], no transpose): 32 k x 128 n = 1024 float4, 4/thread
#pragma unroll
        for (int i = 0; i < 4; i++) {
            const int e  = tid + i * 256;
            const int kk = e >> 5;
            const int n4 = (e & 31) * 4;
            const float* src = W + (size_t)(k0 + kk) * D_ + n0 + n4;
            CP_ASYNC16(sb + (uint32_t)(kk * GB_STRIDE + n4) * 4, src);
        }
        CP_COMMIT();
    };

    load_chunk(0, 0);

#pragma unroll 1
    for (int c = 0; c < G_NC; c++) {
        const int s = c & 1;
        if (c + 1 < G_NC) {
            load_chunk(c + 1, s ^ 1);
            CP_WAIT1();
        } else {
            CP_WAIT0();
        }
        __syncthreads();               // stage s loaded CTA-wide

        const float (*As)[GA_STRIDE] = (const float(*)[GA_STRIDE])(smc + GA_OFF(s));
        const float (*Bs)[GB_STRIDE] = (const float(*)[GB_STRIDE])(smc + GB_OFF(s));

#pragma unroll
        for (int k8 = 0; k8 < 4; k8++) {
            const int k0 = k8 * 8;
            uint32_t bf[4][2];
#pragma unroll
            for (int nt = 0; nt < 4; nt++) {
                bf[nt][0] = f2tf32(Bs[k0 + qq][cb + nt * 8 + g]);
                bf[nt][1] = f2tf32(Bs[k0 + qq + 4][cb + nt * 8 + g]);
            }
#pragma unroll
            for (int mt = 0; mt < 4; mt++) {
                const int r = rb + mt * 16 + g;
                uint32_t a0 = f2tf32(As[r][k0 + qq]);
                uint32_t a1 = f2tf32(As[r + 8][k0 + qq]);
                uint32_t a2 = f2tf32(As[r][k0 + qq + 4]);
                uint32_t a3 = f2tf32(As[r + 8][k0 + qq + 4]);
#pragma unroll
                for (int nt = 0; nt < 4; nt++)
                    mma_tf32(acc[mt][nt], a0, a1, a2, a3, bf[nt][0], bf[nt][1]);
            }
        }
        __syncthreads();               // all reads of stage s done before c+2 overwrites
    }

    // ---- epilogue: bias + float2 stores (c-fragment layout) ----
#pragma unroll
    for (int mt = 0; mt < 4; mt++) {
#pragma unroll
        for (int half = 0; half < 2; half++) {
            const int m  = m0 + rb + mt * 16 + half * 8 + g;
            const int bb = m / S_;
            const int ss = m % S_;
#pragma unroll
            for (int nt = 0; nt < 4; nt++) {
                const int gc = n0 + cb + nt * 8 + 2 * qq;
                float2 o;
                o.x = acc[mt][nt][half * 2 + 0] + bias[gc];
                o.y = acc[mt][nt][half * 2 + 1] + bias[gc + 1];
                if (MODE == 0) {
                    const int h = gc >> 6;
                    const int d = gc & 63;
                    *(float2*)(dstq + ((((size_t)bb * H_ + h) * S_ + ss) << 6) + d) = o;
                } else {
                    *(float2*)(Cout + (size_t)m * D_ + gc) = o;
                }
            }
        }
    }
}

// ---------------------------------------------------------------------------
// Flash attention v2 (causal, fp32): register-tiled micro-GEMMs. (unchanged)
// ---------------------------------------------------------------------------
#define QS_OFF 0
#define KS_OFF (64 * 132)
#define VS_OFF (KS_OFF + 64 * 68)
#define PS_OFF (VS_OFF + 64 * 68)
#define SMEM_FLOATS (PS_OFF + 128 * 68)

__global__ void __launch_bounds__(256)
attn_kernel()
{
    extern __shared__ float sm[];
    float (*Qs)[132] = (float(*)[132])(sm + QS_OFF);
    float (*Ks)[68]  = (float(*)[68])(sm + KS_OFF);
    float (*Vs)[68]  = (float(*)[68])(sm + VS_OFF);
    float (*Ps)[68]  = (float(*)[68])(sm + PS_OFF);

    const int qt  = blockIdx.x;
    const int bh  = blockIdx.y;
    const int b   = bh >> 4;
    const int h   = bh & 15;
    const int tid = threadIdx.x;
    const int tx  = tid & 15;
    const int ty  = tid >> 4;
    const int q0  = qt * 128;

    const float* Qp = g_q + (size_t)bh * S_ * HD_;
    const float* Kp = g_k + (size_t)bh * S_ * HD_;
    const float* Vp = g_v + (size_t)bh * S_ * HD_;

#pragma unroll
    for (int i = 0; i < 8; i++) {
        const int e  = tid + i * 256;
        const int r  = e & 127;
        const int k4 = e >> 7;
        float4 qv = *(const float4*)(Qp + (size_t)(q0 + r) * HD_ + k4 * 4);
        Qs[k4 * 4 + 0][r] = qv.x * 0.125f;
        Qs[k4 * 4 + 1][r] = qv.y * 0.125f;
        Qs[k4 * 4 + 2][r] = qv.z * 0.125f;
        Qs[k4 * 4 + 3][r] = qv.w * 0.125f;
    }

    float m_i[8], l_i[8];
    float O[8][4];
#pragma unroll
    for (int i = 0; i < 8; i++) {
        m_i[i] = -1e30f; l_i[i] = 0.f;
#pragma unroll
        for (int j = 0; j < 4; j++) O[i][j] = 0.f;
    }

    const int ntiles = 2 * qt + 2;
    for (int t = 0; t < ntiles; t++) {
        const int k0 = t * 64;
        __syncthreads();
#pragma unroll
        for (int i = 0; i < 4; i++) {
            const int e  = tid + i * 256;
            const int c  = e & 63;
            const int k4 = e >> 6;
            float4 kv = *(const float4*)(Kp + (size_t)(k0 + c) * HD_ + k4 * 4);
            Ks[k4 * 4 + 0][c] = kv.x;
            Ks[k4 * 4 + 1][c] = kv.y;
            Ks[k4 * 4 + 2][c] = kv.z;
            Ks[k4 * 4 + 3][c] = kv.w;
            const int vc = e >> 4;
            const int d4 = e & 15;
            float4 vv = *(const float4*)(Vp + (size_t)(k0 + vc) * HD_ + d4 * 4);
            *(float4*)&Vs[vc][d4 * 4] = vv;
        }
        __syncthreads();

        float sc[8][4];
#pragma unroll
        for (int i = 0; i < 8; i++)
#pragma unroll
            for (int j = 0; j < 4; j++) sc[i][j] = 0.f;

#pragma unroll 8
        for (int k = 0; k < 64; k++) {
            float rm[8], rn[4];
            *(float4*)&rm[0] = *(const float4*)&Qs[k][ty * 8];
            *(float4*)&rm[4] = *(const float4*)&Qs[k][ty * 8 + 4];
            *(float4*)&rn[0] = *(const float4*)&Ks[k][tx * 4];
#pragma unroll
            for (int i = 0; i < 8; i++)
#pragma unroll
                for (int j = 0; j < 4; j++)
                    sc[i][j] += rm[i] * rn[j];
        }

        if (t + 2 >= ntiles) {
#pragma unroll
            for (int i = 0; i < 8; i++) {
                const int qi = q0 + ty * 8 + i;
#pragma unroll
                for (int j = 0; j < 4; j++)
                    if (k0 + tx * 4 + j > qi) sc[i][j] = -1e30f;
            }
        }

        float mx[8];
#pragma unroll
        for (int i = 0; i < 8; i++) {
            float v = fmaxf(fmaxf(sc[i][0], sc[i][1]), fmaxf(sc[i][2], sc[i][3]));
            v = fmaxf(v, __shfl_xor_sync(0xffffffffu, v, 1));
            v = fmaxf(v, __shfl_xor_sync(0xffffffffu, v, 2));
            v = fmaxf(v, __shfl_xor_sync(0xffffffffu, v, 4));
            v = fmaxf(v, __shfl_xor_sync(0xffffffffu, v, 8));
            mx[i] = v;
        }
#pragma unroll
        for (int i = 0; i < 8; i++) {
            const float m_new = fmaxf(m_i[i], mx[i]);
            const float alpha = __expf(m_i[i] - m_new);
            float p0 = __expf(sc[i][0] - m_new);
            float p1 = __expf(sc[i][1] - m_new);
            float p2 = __expf(sc[i][2] - m_new);
            float p3 = __expf(sc[i][3] - m_new);
            *(float4*)&Ps[ty * 8 + i][tx * 4] = make_float4(p0, p1, p2, p3);
            float ls = (p0 + p1) + (p2 + p3);
            ls += __shfl_xor_sync(0xffffffffu, ls, 1);
            ls += __shfl_xor_sync(0xffffffffu, ls, 2);
            ls += __shfl_xor_sync(0xffffffffu, ls, 4);
            ls += __shfl_xor_sync(0xffffffffu, ls, 8);
            l_i[i] = l_i[i] * alpha + ls;
            m_i[i] = m_new;
            O[i][0] *= alpha; O[i][1] *= alpha;
            O[i][2] *= alpha; O[i][3] *= alpha;
        }
        __syncthreads();

#pragma unroll 1
        for (int c4 = 0; c4 < 16; c4++) {
            const int c = c4 * 4;
            float v0[4], v1[4], v2[4], v3[4];
            *(float4*)&v0[0] = *(const float4*)&Vs[c + 0][tx * 4];
            *(float4*)&v1[0] = *(const float4*)&Vs[c + 1][tx * 4];
            *(float4*)&v2[0] = *(const float4*)&Vs[c + 2][tx * 4];
            *(float4*)&v3[0] = *(const float4*)&Vs[c + 3][tx * 4];
#pragma unroll
            for (int i = 0; i < 8; i++) {
                float4 pm = *(const float4*)&Ps[ty * 8 + i][c];
#pragma unroll
                for (int j = 0; j < 4; j++)
                    O[i][j] += pm.x * v0[j] + pm.y * v1[j] + pm.z * v2[j] + pm.w * v3[j];
            }
        }
    }

#pragma unroll
    for (int i = 0; i < 8; i++) {
        const float inv = 1.f / l_i[i];
        const int qi = q0 + ty * 8 + i;
        float4 o;
        o.x = O[i][0] * inv; o.y = O[i][1] * inv;
        o.z = O[i][2] * inv; o.w = O[i][3] * inv;
        *(float4*)(g_attn + ((size_t)(b * S_ + qi)) * D_ + h * HD_ + tx * 4) = o;
    }
}

// ---------------------------------------------------------------------------
extern "C" void kernel_launch(void* const* d_in, const int* in_sizes, int n_in,
                              void* d_out, int out_size)
{
    const float* x  = (const float*)d_in[0];
    const float* wq = (const float*)d_in[1];
    const float* bq = (const float*)d_in[2];
    const float* wk = (const float*)d_in[3];
    const float* bk = (const float*)d_in[4];
    const float* wv = (const float*)d_in[5];
    const float* bv = (const float*)d_in[6];
    const float* wo = (const float*)d_in[7];
    const float* bo = (const float*)d_in[8];
    float* out = (float*)d_out;

    cudaFuncSetAttribute(attn_kernel,
                         cudaFuncAttributeMaxDynamicSharedMemorySize,
                         SMEM_FLOATS * (int)sizeof(float));
    cudaFuncSetAttribute(gemm_tc<0>,
                         cudaFuncAttributeMaxDynamicSharedMemorySize, G_SMEM);
    cudaFuncSetAttribute(gemm_tc<1>,
                         cudaFuncAttributeMaxDynamicSharedMemorySize, G_SMEM);

    // 1) fused QKV projections (tf32 mma.sync) -> g_q/g_k/g_v in [B,H,S,hd]
    dim3 gq(D_ / 128, M_ / 128, 3);
    gemm_tc<0><<<gq, 256, G_SMEM>>>(x, wq, bq, wk, bk, wv, bv, nullptr);

    // 2) causal flash attention (fp32) -> g_attn in [B,S,D]
    dim3 ga(S_ / 128, B_ * H_);
    attn_kernel<<<ga, 256, SMEM_FLOATS * (int)sizeof(float)>>>();

    // 3) output projection (tf32 mma.sync) -> d_out
    dim3 go(D_ / 128, M_ / 128, 1);
    gemm_tc<1><<<go, 256, G_SMEM>>>(nullptr, wo, bo, nullptr, nullptr, nullptr, nullptr, out);
}

// round 13
// speedup vs baseline: 3.3793x; 1.9011x over previous
#include <cuda_runtime.h>
#include <math.h>
#include <stdint.h>

#define B_  2
#define S_  2048
#define D_  1024
#define H_  16
#define HD_ 64
#define M_  (B_ * S_)   // 4096

// ---------------- scratch (device globals; no runtime allocation) ----------
__device__ float g_q[(size_t)B_ * H_ * S_ * HD_];     // [B,H,S,hd]
__device__ float g_k[(size_t)B_ * H_ * S_ * HD_];
__device__ float g_v[(size_t)B_ * H_ * S_ * HD_];
__device__ float g_attn[(size_t)M_ * D_];             // [B,S,H,hd] == [B,S,D]

// ======================= helpers ===========================================
__device__ __forceinline__ uint32_t smem_u32(const void* p) {
    uint32_t a;
    asm("{ .reg .u64 t; cvta.to.shared.u64 t, %1; cvt.u32.u64 %0, t; }"
        : "=r"(a) : "l"(p));
    return a;
}
__device__ __forceinline__ uint32_t f2tf32(float f) {
    uint32_t r;
    asm("cvt.rna.tf32.f32 %0, %1;" : "=r"(r) : "f"(f));
    return r;
}
#define CP_ASYNC16(dst, src) \
    asm volatile("cp.async.cg.shared.global [%0], [%1], 16;" \
                 :: "r"(dst), "l"(src) : "memory")
#define CP_COMMIT() asm volatile("cp.async.commit_group;" ::: "memory")
#define CP_WAIT0()  asm volatile("cp.async.wait_group 0;" ::: "memory")
#define CP_WAIT1()  asm volatile("cp.async.wait_group 1;" ::: "memory")

__device__ __forceinline__ void mma_tf32(float* c, uint32_t a0, uint32_t a1,
                                         uint32_t a2, uint32_t a3,
                                         uint32_t b0, uint32_t b1) {
    asm volatile(
        "mma.sync.aligned.m16n8k8.row.col.f32.tf32.tf32.f32 "
        "{%0,%1,%2,%3}, {%4,%5,%6,%7}, {%8,%9}, {%0,%1,%2,%3};"
        : "+f"(c[0]), "+f"(c[1]), "+f"(c[2]), "+f"(c[3])
        : "r"(a0), "r"(a1), "r"(a2), "r"(a3), "r"(b0), "r"(b1));
}

// ======================= tf32 mma.sync GEMM (unchanged from R12) ===========
#define GA_STRIDE 36
#define GB_STRIDE 136
#define GA_BYTES (128 * GA_STRIDE * 4)
#define GB_BYTES (32 * GB_STRIDE * 4)
#define GSTAGE   (GA_BYTES + GB_BYTES)
#define GA_OFF(s) ((s) * GSTAGE)
#define GB_OFF(s) ((s) * GSTAGE + GA_BYTES)
#define G_SMEM    (2 * GSTAGE)
#define G_NC      (D_ / 32)

template <int MODE>
__global__ void __launch_bounds__(256)
gemm_tc(const float* __restrict__ A,
        const float* __restrict__ W0, const float* __restrict__ bias0,
        const float* __restrict__ W1, const float* __restrict__ bias1,
        const float* __restrict__ W2, const float* __restrict__ bias2,
        float* __restrict__ Cout)
{
    extern __shared__ char smc[];
    const uint32_t smb = smem_u32(smc);

    const float* W    = W0;
    const float* bias = bias0;
    float*       dstq = nullptr;
    if (MODE == 0) {
        if (blockIdx.z == 0)      { W = W0; bias = bias0; dstq = g_q; }
        else if (blockIdx.z == 1) { W = W1; bias = bias1; dstq = g_k; }
        else                      { W = W2; bias = bias2; dstq = g_v; }
    }
    const float* Ab = (MODE == 0) ? A : (const float*)g_attn;

    const int tid    = threadIdx.x;
    const int lid    = tid & 31;
    const int wid    = tid >> 5;
    const int warp_m = wid >> 2;
    const int warp_n = wid & 3;
    const int g      = lid >> 2;
    const int qq     = lid & 3;
    const int m0     = blockIdx.y * 128;
    const int n0     = blockIdx.x * 128;
    const int rb     = warp_m * 64;
    const int cb     = warp_n * 32;

    float acc[4][4][4];
#pragma unroll
    for (int mt = 0; mt < 4; mt++)
#pragma unroll
        for (int nt = 0; nt < 4; nt++)
#pragma unroll
            for (int e = 0; e < 4; e++) acc[mt][nt][e] = 0.f;

    auto load_chunk = [&](int c, int s) {
        const int k0 = c * 32;
        const uint32_t sa = smb + GA_OFF(s);
        const uint32_t sb = smb + GB_OFF(s);
#pragma unroll
        for (int i = 0; i < 4; i++) {
            const int e   = tid + i * 256;
            const int row = e >> 3;
            const int c4  = (e & 7) * 4;
            const float* src = Ab + (size_t)(m0 + row) * D_ + k0 + c4;
            CP_ASYNC16(sa + (uint32_t)(row * GA_STRIDE + c4) * 4, src);
        }
#pragma unroll
        for (int i = 0; i < 4; i++) {
            const int e  = tid + i * 256;
            const int kk = e >> 5;
            const int n4 = (e & 31) * 4;
            const float* src = W + (size_t)(k0 + kk) * D_ + n0 + n4;
            CP_ASYNC16(sb + (uint32_t)(kk * GB_STRIDE + n4) * 4, src);
        }
        CP_COMMIT();
    };

    load_chunk(0, 0);

#pragma unroll 1
    for (int c = 0; c < G_NC; c++) {
        const int s = c & 1;
        if (c + 1 < G_NC) {
            load_chunk(c + 1, s ^ 1);
            CP_WAIT1();
        } else {
            CP_WAIT0();
        }
        __syncthreads();

        const float (*As)[GA_STRIDE] = (const float(*)[GA_STRIDE])(smc + GA_OFF(s));
        const float (*Bs)[GB_STRIDE] = (const float(*)[GB_STRIDE])(smc + GB_OFF(s));

#pragma unroll
        for (int k8 = 0; k8 < 4; k8++) {
            const int k0 = k8 * 8;
            uint32_t bf[4][2];
#pragma unroll
            for (int nt = 0; nt < 4; nt++) {
                bf[nt][0] = f2tf32(Bs[k0 + qq][cb + nt * 8 + g]);
                bf[nt][1] = f2tf32(Bs[k0 + qq + 4][cb + nt * 8 + g]);
            }
#pragma unroll
            for (int mt = 0; mt < 4; mt++) {
                const int r = rb + mt * 16 + g;
                uint32_t a0 = f2tf32(As[r][k0 + qq]);
                uint32_t a1 = f2tf32(As[r + 8][k0 + qq]);
                uint32_t a2 = f2tf32(As[r][k0 + qq + 4]);
                uint32_t a3 = f2tf32(As[r + 8][k0 + qq + 4]);
#pragma unroll
                for (int nt = 0; nt < 4; nt++)
                    mma_tf32(acc[mt][nt], a0, a1, a2, a3, bf[nt][0], bf[nt][1]);
            }
        }
        __syncthreads();
    }

#pragma unroll
    for (int mt = 0; mt < 4; mt++) {
#pragma unroll
        for (int half = 0; half < 2; half++) {
            const int m  = m0 + rb + mt * 16 + half * 8 + g;
            const int bb = m / S_;
            const int ss = m % S_;
#pragma unroll
            for (int nt = 0; nt < 4; nt++) {
                const int gc = n0 + cb + nt * 8 + 2 * qq;
                float2 o;
                o.x = acc[mt][nt][half * 2 + 0] + bias[gc];
                o.y = acc[mt][nt][half * 2 + 1] + bias[gc + 1];
                if (MODE == 0) {
                    const int h = gc >> 6;
                    const int d = gc & 63;
                    *(float2*)(dstq + ((((size_t)bb * H_ + h) * S_ + ss) << 6) + d) = o;
                } else {
                    *(float2*)(Cout + (size_t)m * D_ + gc) = o;
                }
            }
        }
    }
}

// ======================= tf32 mma.sync flash attention =====================
// Block = 128 q rows x one (b,h). 8 warps; warp owns 16 q-rows x full KV tile
// (64): softmax reductions are intra-warp (xor-shfl over qq lanes).
// Q, P stored in smem as pre-converted tf32 bits; K row-major (B-fragment
// indexes it transposed), V row-major. cp.async double-buffered K/V.
// Banking: QS/PS stride 68 (A-frag bank 4g+qq), KS stride 68 (B-frag 4g+qq),
// VS stride 72 (B-frag 8qq+g) — all conflict-free.
#define AQ_OFF 0
#define AP_OFF (128 * 68)
#define AK_OFF(s) (2 * 128 * 68 + (s) * 64 * 68)
#define AV_OFF(s) (2 * 128 * 68 + 2 * 64 * 68 + (s) * 64 * 72)
#define A_SMEM_FLOATS (2 * 128 * 68 + 2 * 64 * 68 + 2 * 64 * 72)  // 35328

__global__ void __launch_bounds__(256)
attn_kernel()
{
    extern __shared__ float sm[];
    const uint32_t smb = smem_u32(sm);
    uint32_t* QS = (uint32_t*)sm + AQ_OFF;   // [128][68] tf32 bits
    uint32_t* PS = (uint32_t*)sm + AP_OFF;   // [128][68] tf32 bits

    const int qt  = blockIdx.x;
    const int bh  = blockIdx.y;
    const int b   = bh >> 4;
    const int h   = bh & 15;
    const int tid = threadIdx.x;
    const int lid = tid & 31;
    const int wid = tid >> 5;
    const int g   = lid >> 2;
    const int qq  = lid & 3;
    const int q0  = qt * 128;
    const int rw  = wid * 16 + g;        // warp-local q row (and +8)

    const float* Qp = g_q + (size_t)bh * S_ * HD_;
    const float* Kp = g_k + (size_t)bh * S_ * HD_;
    const float* Vp = g_v + (size_t)bh * S_ * HD_;

    // ---- load Q once: scale by 1/8, convert to tf32 bits ----
#pragma unroll
    for (int i = 0; i < 8; i++) {
        const int e   = tid + i * 256;   // 0..2047
        const int row = e >> 4;
        const int c4  = (e & 15) * 4;
        float4 qv = *(const float4*)(Qp + (size_t)(q0 + row) * HD_ + c4);
        uint32_t* d = QS + row * 68 + c4;
        d[0] = f2tf32(qv.x * 0.125f);
        d[1] = f2tf32(qv.y * 0.125f);
        d[2] = f2tf32(qv.z * 0.125f);
        d[3] = f2tf32(qv.w * 0.125f);
    }

    // ---- K/V tile loader (cp.async, raw fp32) ----
    auto load_kv = [&](int t, int s) {
        const int k0 = t * 64;
        const uint32_t ks = smb + (AK_OFF(s)) * 4;
        const uint32_t vs = smb + (AV_OFF(s)) * 4;
#pragma unroll
        for (int i = 0; i < 4; i++) {
            const int e   = tid + i * 256;   // 0..1023
            const int row = e >> 4;
            const int c4  = (e & 15) * 4;
            CP_ASYNC16(ks + (uint32_t)(row * 68 + c4) * 4,
                       Kp + (size_t)(k0 + row) * HD_ + c4);
            CP_ASYNC16(vs + (uint32_t)(row * 72 + c4) * 4,
                       Vp + (size_t)(k0 + row) * HD_ + c4);
        }
        CP_COMMIT();
    };

    float m0 = -1e30f, m1 = -1e30f, l0 = 0.f, l1 = 0.f;
    float O[8][4];
#pragma unroll
    for (int nt = 0; nt < 8; nt++)
#pragma unroll
        for (int e = 0; e < 4; e++) O[nt][e] = 0.f;

    load_kv(0, 0);

    const int ntiles = 2 * qt + 2;   // causal
#pragma unroll 1
    for (int t = 0; t < ntiles; t++) {
        const int s = t & 1;
        if (t + 1 < ntiles) {
            load_kv(t + 1, s ^ 1);
            CP_WAIT1();
        } else {
            CP_WAIT0();
        }
        __syncthreads();   // stage s resident; Q ready (t==0)

        const float (*KS)[68] = (const float(*)[68])(sm + AK_OFF(s));
        const float (*VS)[72] = (const float(*)[72])(sm + AV_OFF(s));

        // ---- scores: S = Q K^T via mma (warp rows rw, rw+8; 8 n-tiles) ----
        float sc[8][4];
#pragma unroll
        for (int nt = 0; nt < 8; nt++)
#pragma unroll
            for (int e = 0; e < 4; e++) sc[nt][e] = 0.f;

#pragma unroll
        for (int kk = 0; kk < 8; kk++) {
            const int k = kk * 8 + qq;
            uint32_t a0 = QS[rw * 68 + k];
            uint32_t a1 = QS[(rw + 8) * 68 + k];
            uint32_t a2 = QS[rw * 68 + k + 4];
            uint32_t a3 = QS[(rw + 8) * 68 + k + 4];
#pragma unroll
            for (int nt = 0; nt < 8; nt++) {
                uint32_t b0 = f2tf32(KS[nt * 8 + g][k]);
                uint32_t b1 = f2tf32(KS[nt * 8 + g][k + 4]);
                mma_tf32(sc[nt], a0, a1, a2, a3, b0, b1);
            }
        }

        // ---- causal mask (only last two tiles touch the diagonal) ----
        const int k0g = t * 64;
        if (t + 2 >= ntiles) {
            const int qi0 = q0 + rw;
            const int qi1 = qi0 + 8;
#pragma unroll
            for (int nt = 0; nt < 8; nt++) {
                const int c0 = k0g + nt * 8 + 2 * qq;
                if (c0 > qi0)     sc[nt][0] = -1e30f;
                if (c0 + 1 > qi0) sc[nt][1] = -1e30f;
                if (c0 > qi1)     sc[nt][2] = -1e30f;
                if (c0 + 1 > qi1) sc[nt][3] = -1e30f;
            }
        }

        // ---- online softmax (rows rw, rw+8; reduce over qq lanes) ----
        float mx0 = -1e30f, mx1 = -1e30f;
#pragma unroll
        for (int nt = 0; nt < 8; nt++) {
            mx0 = fmaxf(mx0, fmaxf(sc[nt][0], sc[nt][1]));
            mx1 = fmaxf(mx1, fmaxf(sc[nt][2], sc[nt][3]));
        }
        mx0 = fmaxf(mx0, __shfl_xor_sync(0xffffffffu, mx0, 1));
        mx0 = fmaxf(mx0, __shfl_xor_sync(0xffffffffu, mx0, 2));
        mx1 = fmaxf(mx1, __shfl_xor_sync(0xffffffffu, mx1, 1));
        mx1 = fmaxf(mx1, __shfl_xor_sync(0xffffffffu, mx1, 2));

        const float mn0 = fmaxf(m0, mx0);
        const float mn1 = fmaxf(m1, mx1);
        const float al0 = __expf(m0 - mn0);
        const float al1 = __expf(m1 - mn1);

        float ls0 = 0.f, ls1 = 0.f;
#pragma unroll
        for (int nt = 0; nt < 8; nt++) {
            float p00 = __expf(sc[nt][0] - mn0);
            float p01 = __expf(sc[nt][1] - mn0);
            float p10 = __expf(sc[nt][2] - mn1);
            float p11 = __expf(sc[nt][3] - mn1);
            ls0 += p00 + p01;
            ls1 += p10 + p11;
            uint2 w0 = make_uint2(f2tf32(p00), f2tf32(p01));
            uint2 w1 = make_uint2(f2tf32(p10), f2tf32(p11));
            *(uint2*)(PS + rw * 68 + nt * 8 + 2 * qq) = w0;
            *(uint2*)(PS + (rw + 8) * 68 + nt * 8 + 2 * qq) = w1;
        }
        ls0 += __shfl_xor_sync(0xffffffffu, ls0, 1);
        ls0 += __shfl_xor_sync(0xffffffffu, ls0, 2);
        ls1 += __shfl_xor_sync(0xffffffffu, ls1, 1);
        ls1 += __shfl_xor_sync(0xffffffffu, ls1, 2);
        l0 = l0 * al0 + ls0;
        l1 = l1 * al1 + ls1;
        m0 = mn0; m1 = mn1;
#pragma unroll
        for (int nt = 0; nt < 8; nt++) {
            O[nt][0] *= al0; O[nt][1] *= al0;
            O[nt][2] *= al1; O[nt][3] *= al1;
        }
        __syncwarp();   // PS rows are warp-private: order STS -> LDS

        // ---- O += P V via mma ----
#pragma unroll
        for (int kk = 0; kk < 8; kk++) {
            const int k = kk * 8 + qq;
            uint32_t a0 = PS[rw * 68 + k];
            uint32_t a1 = PS[(rw + 8) * 68 + k];
            uint32_t a2 = PS[rw * 68 + k + 4];
            uint32_t a3 = PS[(rw + 8) * 68 + k + 4];
#pragma unroll
            for (int nt = 0; nt < 8; nt++) {
                uint32_t b0 = f2tf32(VS[kk * 8 + qq][nt * 8 + g]);
                uint32_t b1 = f2tf32(VS[kk * 8 + qq + 4][nt * 8 + g]);
                mma_tf32(O[nt], a0, a1, a2, a3, b0, b1);
            }
        }
        __syncthreads();   // stage reads done before next tile's cp.async
    }

    // ---- finalize: /l, write to [B,S,H,hd] (== [B,S,D]) ----
    const float inv0 = 1.f / l0;
    const float inv1 = 1.f / l1;
    const int qg0 = q0 + rw;
    float* d0 = g_attn + ((size_t)(b * S_ + qg0)) * D_ + h * HD_;
    float* d1 = d0 + (size_t)8 * D_;
#pragma unroll
    for (int nt = 0; nt < 8; nt++) {
        const int col = nt * 8 + 2 * qq;
        *(float2*)(d0 + col) = make_float2(O[nt][0] * inv0, O[nt][1] * inv0);
        *(float2*)(d1 + col) = make_float2(O[nt][2] * inv1, O[nt][3] * inv1);
    }
}

// ---------------------------------------------------------------------------
extern "C" void kernel_launch(void* const* d_in, const int* in_sizes, int n_in,
                              void* d_out, int out_size)
{
    const float* x  = (const float*)d_in[0];
    const float* wq = (const float*)d_in[1];
    const float* bq = (const float*)d_in[2];
    const float* wk = (const float*)d_in[3];
    const float* bk = (const float*)d_in[4];
    const float* wv = (const float*)d_in[5];
    const float* bv = (const float*)d_in[6];
    const float* wo = (const float*)d_in[7];
    const float* bo = (const float*)d_in[8];
    float* out = (float*)d_out;

    cudaFuncSetAttribute(attn_kernel,
                         cudaFuncAttributeMaxDynamicSharedMemorySize,
                         A_SMEM_FLOATS * (int)sizeof(float));
    cudaFuncSetAttribute(gemm_tc<0>,
                         cudaFuncAttributeMaxDynamicSharedMemorySize, G_SMEM);
    cudaFuncSetAttribute(gemm_tc<1>,
                         cudaFuncAttributeMaxDynamicSharedMemorySize, G_SMEM);

    // 1) fused QKV projections (tf32 mma.sync) -> g_q/g_k/g_v in [B,H,S,hd]
    dim3 gq(D_ / 128, M_ / 128, 3);
    gemm_tc<0><<<gq, 256, G_SMEM>>>(x, wq, bq, wk, bk, wv, bv, nullptr);

    // 2) causal flash attention (tf32 mma.sync) -> g_attn in [B,S,D]
    dim3 ga(S_ / 128, B_ * H_);
    attn_kernel<<<ga, 256, A_SMEM_FLOATS * (int)sizeof(float)>>>();

    // 3) output projection (tf32 mma.sync) -> d_out
    dim3 go(D_ / 128, M_ / 128, 1);
    gemm_tc<1><<<go, 256, G_SMEM>>>(nullptr, wo, bo, nullptr, nullptr, nullptr, nullptr, out);
}

// round 14
// speedup vs baseline: 3.3859x; 1.0019x over previous
#include <cuda_runtime.h>
#include <math.h>
#include <stdint.h>

#define B_  2
#define S_  2048
#define D_  1024
#define H_  16
#define HD_ 64
#define M_  (B_ * S_)   // 4096

// ---------------- scratch (device globals; no runtime allocation) ----------
__device__ float g_q[(size_t)B_ * H_ * S_ * HD_];     // [B,H,S,hd]
__device__ float g_k[(size_t)B_ * H_ * S_ * HD_];
__device__ float g_v[(size_t)B_ * H_ * S_ * HD_];
__device__ float g_attn[(size_t)M_ * D_];             // [B,S,H,hd] == [B,S,D]

// ======================= helpers ===========================================
__device__ __forceinline__ uint32_t smem_u32(const void* p) {
    uint32_t a;
    asm("{ .reg .u64 t; cvta.to.shared.u64 t, %1; cvt.u32.u64 %0, t; }"
        : "=r"(a) : "l"(p));
    return a;
}
__device__ __forceinline__ uint32_t f2tf32(float f) {
    uint32_t r;
    asm("cvt.rna.tf32.f32 %0, %1;" : "=r"(r) : "f"(f));
    return r;
}
#define CP_ASYNC16(dst, src) \
    asm volatile("cp.async.cg.shared.global [%0], [%1], 16;" \
                 :: "r"(dst), "l"(src) : "memory")
#define CP_COMMIT() asm volatile("cp.async.commit_group;" ::: "memory")
#define CP_WAIT0()  asm volatile("cp.async.wait_group 0;" ::: "memory")
#define CP_WAIT1()  asm volatile("cp.async.wait_group 1;" ::: "memory")

__device__ __forceinline__ void mma_tf32(float* c, uint32_t a0, uint32_t a1,
                                         uint32_t a2, uint32_t a3,
                                         uint32_t b0, uint32_t b1) {
    asm volatile(
        "mma.sync.aligned.m16n8k8.row.col.f32.tf32.tf32.f32 "
        "{%0,%1,%2,%3}, {%4,%5,%6,%7}, {%8,%9}, {%0,%1,%2,%3};"
        : "+f"(c[0]), "+f"(c[1]), "+f"(c[2]), "+f"(c[3])
        : "r"(a0), "r"(a1), "r"(a2), "r"(a3), "r"(b0), "r"(b1));
}

// ======================= tf32 mma.sync GEMM (unchanged from R12) ===========
#define GA_STRIDE 36
#define GB_STRIDE 136
#define GA_BYTES (128 * GA_STRIDE * 4)
#define GB_BYTES (32 * GB_STRIDE * 4)
#define GSTAGE   (GA_BYTES + GB_BYTES)
#define GA_OFF(s) ((s) * GSTAGE)
#define GB_OFF(s) ((s) * GSTAGE + GA_BYTES)
#define G_SMEM    (2 * GSTAGE)
#define G_NC      (D_ / 32)

template <int MODE>
__global__ void __launch_bounds__(256)
gemm_tc(const float* __restrict__ A,
        const float* __restrict__ W0, const float* __restrict__ bias0,
        const float* __restrict__ W1, const float* __restrict__ bias1,
        const float* __restrict__ W2, const float* __restrict__ bias2,
        float* __restrict__ Cout)
{
    extern __shared__ char smc[];
    const uint32_t smb = smem_u32(smc);

    const float* W    = W0;
    const float* bias = bias0;
    float*       dstq = nullptr;
    if (MODE == 0) {
        if (blockIdx.z == 0)      { W = W0; bias = bias0; dstq = g_q; }
        else if (blockIdx.z == 1) { W = W1; bias = bias1; dstq = g_k; }
        else                      { W = W2; bias = bias2; dstq = g_v; }
    }
    const float* Ab = (MODE == 0) ? A : (const float*)g_attn;

    const int tid    = threadIdx.x;
    const int lid    = tid & 31;
    const int wid    = tid >> 5;
    const int warp_m = wid >> 2;
    const int warp_n = wid & 3;
    const int g      = lid >> 2;
    const int qq     = lid & 3;
    const int m0     = blockIdx.y * 128;
    const int n0     = blockIdx.x * 128;
    const int rb     = warp_m * 64;
    const int cb     = warp_n * 32;

    float acc[4][4][4];
#pragma unroll
    for (int mt = 0; mt < 4; mt++)
#pragma unroll
        for (int nt = 0; nt < 4; nt++)
#pragma unroll
            for (int e = 0; e < 4; e++) acc[mt][nt][e] = 0.f;

    auto load_chunk = [&](int c, int s) {
        const int k0 = c * 32;
        const uint32_t sa = smb + GA_OFF(s);
        const uint32_t sb = smb + GB_OFF(s);
#pragma unroll
        for (int i = 0; i < 4; i++) {
            const int e   = tid + i * 256;
            const int row = e >> 3;
            const int c4  = (e & 7) * 4;
            const float* src = Ab + (size_t)(m0 + row) * D_ + k0 + c4;
            CP_ASYNC16(sa + (uint32_t)(row * GA_STRIDE + c4) * 4, src);
        }
#pragma unroll
        for (int i = 0; i < 4; i++) {
            const int e  = tid + i * 256;
            const int kk = e >> 5;
            const int n4 = (e & 31) * 4;
            const float* src = W + (size_t)(k0 + kk) * D_ + n0 + n4;
            CP_ASYNC16(sb + (uint32_t)(kk * GB_STRIDE + n4) * 4, src);
        }
        CP_COMMIT();
    };

    load_chunk(0, 0);

#pragma unroll 1
    for (int c = 0; c < G_NC; c++) {
        const int s = c & 1;
        if (c + 1 < G_NC) {
            load_chunk(c + 1, s ^ 1);
            CP_WAIT1();
        } else {
            CP_WAIT0();
        }
        __syncthreads();

        const float (*As)[GA_STRIDE] = (const float(*)[GA_STRIDE])(smc + GA_OFF(s));
        const float (*Bs)[GB_STRIDE] = (const float(*)[GB_STRIDE])(smc + GB_OFF(s));

#pragma unroll
        for (int k8 = 0; k8 < 4; k8++) {
            const int k0 = k8 * 8;
            uint32_t bf[4][2];
#pragma unroll
            for (int nt = 0; nt < 4; nt++) {
                bf[nt][0] = f2tf32(Bs[k0 + qq][cb + nt * 8 + g]);
                bf[nt][1] = f2tf32(Bs[k0 + qq + 4][cb + nt * 8 + g]);
            }
#pragma unroll
            for (int mt = 0; mt < 4; mt++) {
                const int r = rb + mt * 16 + g;
                uint32_t a0 = f2tf32(As[r][k0 + qq]);
                uint32_t a1 = f2tf32(As[r + 8][k0 + qq]);
                uint32_t a2 = f2tf32(As[r][k0 + qq + 4]);
                uint32_t a3 = f2tf32(As[r + 8][k0 + qq + 4]);
#pragma unroll
                for (int nt = 0; nt < 4; nt++)
                    mma_tf32(acc[mt][nt], a0, a1, a2, a3, bf[nt][0], bf[nt][1]);
            }
        }
        __syncthreads();
    }

#pragma unroll
    for (int mt = 0; mt < 4; mt++) {
#pragma unroll
        for (int half = 0; half < 2; half++) {
            const int m  = m0 + rb + mt * 16 + half * 8 + g;
            const int bb = m / S_;
            const int ss = m % S_;
#pragma unroll
            for (int nt = 0; nt < 4; nt++) {
                const int gc = n0 + cb + nt * 8 + 2 * qq;
                float2 o;
                o.x = acc[mt][nt][half * 2 + 0] + bias[gc];
                o.y = acc[mt][nt][half * 2 + 1] + bias[gc + 1];
                if (MODE == 0) {
                    const int h = gc >> 6;
                    const int d = gc & 63;
                    *(float2*)(dstq + ((((size_t)bb * H_ + h) * S_ + ss) << 6) + d) = o;
                } else {
                    *(float2*)(Cout + (size_t)m * D_ + gc) = o;
                }
            }
        }
    }
}

// ======================= tf32 mma.sync flash attention =====================
// Block = 128 q rows x one (b,h). 8 warps; warp owns 16 q-rows x full KV tile
// (64): softmax reductions are intra-warp (xor-shfl over qq lanes).
// Q, P stored in smem as pre-converted tf32 bits; K row-major (B-fragment
// indexes it transposed), V row-major. cp.async double-buffered K/V.
// Banking: QS/PS stride 68 (A-frag bank 4g+qq), KS stride 68 (B-frag 4g+qq),
// VS stride 72 (B-frag 8qq+g) — all conflict-free.
#define AQ_OFF 0
#define AP_OFF (128 * 68)
#define AK_OFF(s) (2 * 128 * 68 + (s) * 64 * 68)
#define AV_OFF(s) (2 * 128 * 68 + 2 * 64 * 68 + (s) * 64 * 72)
#define A_SMEM_FLOATS (2 * 128 * 68 + 2 * 64 * 68 + 2 * 64 * 72)  // 35328

__global__ void __launch_bounds__(256)
attn_kernel()
{
    extern __shared__ float sm[];
    const uint32_t smb = smem_u32(sm);
    uint32_t* QS = (uint32_t*)sm + AQ_OFF;   // [128][68] tf32 bits
    uint32_t* PS = (uint32_t*)sm + AP_OFF;   // [128][68] tf32 bits

    const int qt  = blockIdx.x;
    const int bh  = blockIdx.y;
    const int b   = bh >> 4;
    const int h   = bh & 15;
    const int tid = threadIdx.x;
    const int lid = tid & 31;
    const int wid = tid >> 5;
    const int g   = lid >> 2;
    const int qq  = lid & 3;
    const int q0  = qt * 128;
    const int rw  = wid * 16 + g;        // warp-local q row (and +8)

    const float* Qp = g_q + (size_t)bh * S_ * HD_;
    const float* Kp = g_k + (size_t)bh * S_ * HD_;
    const float* Vp = g_v + (size_t)bh * S_ * HD_;

    // ---- load Q once: scale by 1/8, convert to tf32 bits ----
#pragma unroll
    for (int i = 0; i < 8; i++) {
        const int e   = tid + i * 256;   // 0..2047
        const int row = e >> 4;
        const int c4  = (e & 15) * 4;
        float4 qv = *(const float4*)(Qp + (size_t)(q0 + row) * HD_ + c4);
        uint32_t* d = QS + row * 68 + c4;
        d[0] = f2tf32(qv.x * 0.125f);
        d[1] = f2tf32(qv.y * 0.125f);
        d[2] = f2tf32(qv.z * 0.125f);
        d[3] = f2tf32(qv.w * 0.125f);
    }

    // ---- K/V tile loader (cp.async, raw fp32) ----
    auto load_kv = [&](int t, int s) {
        const int k0 = t * 64;
        const uint32_t ks = smb + (AK_OFF(s)) * 4;
        const uint32_t vs = smb + (AV_OFF(s)) * 4;
#pragma unroll
        for (int i = 0; i < 4; i++) {
            const int e   = tid + i * 256;   // 0..1023
            const int row = e >> 4;
            const int c4  = (e & 15) * 4;
            CP_ASYNC16(ks + (uint32_t)(row * 68 + c4) * 4,
                       Kp + (size_t)(k0 + row) * HD_ + c4);
            CP_ASYNC16(vs + (uint32_t)(row * 72 + c4) * 4,
                       Vp + (size_t)(k0 + row) * HD_ + c4);
        }
        CP_COMMIT();
    };

    float m0 = -1e30f, m1 = -1e30f, l0 = 0.f, l1 = 0.f;
    float O[8][4];
#pragma unroll
    for (int nt = 0; nt < 8; nt++)
#pragma unroll
        for (int e = 0; e < 4; e++) O[nt][e] = 0.f;

    load_kv(0, 0);

    const int ntiles = 2 * qt + 2;   // causal
#pragma unroll 1
    for (int t = 0; t < ntiles; t++) {
        const int s = t & 1;
        if (t + 1 < ntiles) {
            load_kv(t + 1, s ^ 1);
            CP_WAIT1();
        } else {
            CP_WAIT0();
        }
        __syncthreads();   // stage s resident; Q ready (t==0)

        const float (*KS)[68] = (const float(*)[68])(sm + AK_OFF(s));
        const float (*VS)[72] = (const float(*)[72])(sm + AV_OFF(s));

        // ---- scores: S = Q K^T via mma (warp rows rw, rw+8; 8 n-tiles) ----
        float sc[8][4];
#pragma unroll
        for (int nt = 0; nt < 8; nt++)
#pragma unroll
            for (int e = 0; e < 4; e++) sc[nt][e] = 0.f;

#pragma unroll
        for (int kk = 0; kk < 8; kk++) {
            const int k = kk * 8 + qq;
            uint32_t a0 = QS[rw * 68 + k];
            uint32_t a1 = QS[(rw + 8) * 68 + k];
            uint32_t a2 = QS[rw * 68 + k + 4];
            uint32_t a3 = QS[(rw + 8) * 68 + k + 4];
#pragma unroll
            for (int nt = 0; nt < 8; nt++) {
                uint32_t b0 = f2tf32(KS[nt * 8 + g][k]);
                uint32_t b1 = f2tf32(KS[nt * 8 + g][k + 4]);
                mma_tf32(sc[nt], a0, a1, a2, a3, b0, b1);
            }
        }

        // ---- causal mask (only last two tiles touch the diagonal) ----
        const int k0g = t * 64;
        if (t + 2 >= ntiles) {
            const int qi0 = q0 + rw;
            const int qi1 = qi0 + 8;
#pragma unroll
            for (int nt = 0; nt < 8; nt++) {
                const int c0 = k0g + nt * 8 + 2 * qq;
                if (c0 > qi0)     sc[nt][0] = -1e30f;
                if (c0 + 1 > qi0) sc[nt][1] = -1e30f;
                if (c0 > qi1)     sc[nt][2] = -1e30f;
                if (c0 + 1 > qi1) sc[nt][3] = -1e30f;
            }
        }

        // ---- online softmax (rows rw, rw+8; reduce over qq lanes) ----
        float mx0 = -1e30f, mx1 = -1e30f;
#pragma unroll
        for (int nt = 0; nt < 8; nt++) {
            mx0 = fmaxf(mx0, fmaxf(sc[nt][0], sc[nt][1]));
            mx1 = fmaxf(mx1, fmaxf(sc[nt][2], sc[nt][3]));
        }
        mx0 = fmaxf(mx0, __shfl_xor_sync(0xffffffffu, mx0, 1));
        mx0 = fmaxf(mx0, __shfl_xor_sync(0xffffffffu, mx0, 2));
        mx1 = fmaxf(mx1, __shfl_xor_sync(0xffffffffu, mx1, 1));
        mx1 = fmaxf(mx1, __shfl_xor_sync(0xffffffffu, mx1, 2));

        const float mn0 = fmaxf(m0, mx0);
        const float mn1 = fmaxf(m1, mx1);
        const float al0 = __expf(m0 - mn0);
        const float al1 = __expf(m1 - mn1);

        float ls0 = 0.f, ls1 = 0.f;
#pragma unroll
        for (int nt = 0; nt < 8; nt++) {
            float p00 = __expf(sc[nt][0] - mn0);
            float p01 = __expf(sc[nt][1] - mn0);
            float p10 = __expf(sc[nt][2] - mn1);
            float p11 = __expf(sc[nt][3] - mn1);
            ls0 += p00 + p01;
            ls1 += p10 + p11;
            uint2 w0 = make_uint2(f2tf32(p00), f2tf32(p01));
            uint2 w1 = make_uint2(f2tf32(p10), f2tf32(p11));
            *(uint2*)(PS + rw * 68 + nt * 8 + 2 * qq) = w0;
            *(uint2*)(PS + (rw + 8) * 68 + nt * 8 + 2 * qq) = w1;
        }
        ls0 += __shfl_xor_sync(0xffffffffu, ls0, 1);
        ls0 += __shfl_xor_sync(0xffffffffu, ls0, 2);
        ls1 += __shfl_xor_sync(0xffffffffu, ls1, 1);
        ls1 += __shfl_xor_sync(0xffffffffu, ls1, 2);
        l0 = l0 * al0 + ls0;
        l1 = l1 * al1 + ls1;
        m0 = mn0; m1 = mn1;
#pragma unroll
        for (int nt = 0; nt < 8; nt++) {
            O[nt][0] *= al0; O[nt][1] *= al0;
            O[nt][2] *= al1; O[nt][3] *= al1;
        }
        __syncwarp();   // PS rows are warp-private: order STS -> LDS

        // ---- O += P V via mma ----
#pragma unroll
        for (int kk = 0; kk < 8; kk++) {
            const int k = kk * 8 + qq;
            uint32_t a0 = PS[rw * 68 + k];
            uint32_t a1 = PS[(rw + 8) * 68 + k];
            uint32_t a2 = PS[rw * 68 + k + 4];
            uint32_t a3 = PS[(rw + 8) * 68 + k + 4];
#pragma unroll
            for (int nt = 0; nt < 8; nt++) {
                uint32_t b0 = f2tf32(VS[kk * 8 + qq][nt * 8 + g]);
                uint32_t b1 = f2tf32(VS[kk * 8 + qq + 4][nt * 8 + g]);
                mma_tf32(O[nt], a0, a1, a2, a3, b0, b1);
            }
        }
        __syncthreads();   // stage reads done before next tile's cp.async
    }

    // ---- finalize: /l, write to [B,S,H,hd] (== [B,S,D]) ----
    const float inv0 = 1.f / l0;
    const float inv1 = 1.f / l1;
    const int qg0 = q0 + rw;
    float* d0 = g_attn + ((size_t)(b * S_ + qg0)) * D_ + h * HD_;
    float* d1 = d0 + (size_t)8 * D_;
#pragma unroll
    for (int nt = 0; nt < 8; nt++) {
        const int col = nt * 8 + 2 * qq;
        *(float2*)(d0 + col) = make_float2(O[nt][0] * inv0, O[nt][1] * inv0);
        *(float2*)(d1 + col) = make_float2(O[nt][2] * inv1, O[nt][3] * inv1);
    }
}

// ---------------------------------------------------------------------------
extern "C" void kernel_launch(void* const* d_in, const int* in_sizes, int n_in,
                              void* d_out, int out_size)
{
    const float* x  = (const float*)d_in[0];
    const float* wq = (const float*)d_in[1];
    const float* bq = (const float*)d_in[2];
    const float* wk = (const float*)d_in[3];
    const float* bk = (const float*)d_in[4];
    const float* wv = (const float*)d_in[5];
    const float* bv = (const float*)d_in[6];
    const float* wo = (const float*)d_in[7];
    const float* bo = (const float*)d_in[8];
    float* out = (float*)d_out;

    cudaFuncSetAttribute(attn_kernel,
                         cudaFuncAttributeMaxDynamicSharedMemorySize,
                         A_SMEM_FLOATS * (int)sizeof(float));
    cudaFuncSetAttribute(gemm_tc<0>,
                         cudaFuncAttributeMaxDynamicSharedMemorySize, G_SMEM);
    cudaFuncSetAttribute(gemm_tc<1>,
                         cudaFuncAttributeMaxDynamicSharedMemorySize, G_SMEM);

    // 1) fused QKV projections (tf32 mma.sync) -> g_q/g_k/g_v in [B,H,S,hd]
    dim3 gq(D_ / 128, M_ / 128, 3);
    gemm_tc<0><<<gq, 256, G_SMEM>>>(x, wq, bq, wk, bk, wv, bv, nullptr);

    // 2) causal flash attention (tf32 mma.sync) -> g_attn in [B,S,D]
    dim3 ga(S_ / 128, B_ * H_);
    attn_kernel<<<ga, 256, A_SMEM_FLOATS * (int)sizeof(float)>>>();

    // 3) output projection (tf32 mma.sync) -> d_out
    dim3 go(D_ / 128, M_ / 128, 1);
    gemm_tc<1><<<go, 256, G_SMEM>>>(nullptr, wo, bo, nullptr, nullptr, nullptr, nullptr, out);
}

// round 15
// speedup vs baseline: 3.6186x; 1.0687x over previous
#include <cuda_runtime.h>
#include <math.h>
#include <stdint.h>

#define B_  2
#define S_  2048
#define D_  1024
#define H_  16
#define HD_ 64
#define M_  (B_ * S_)   // 4096
#define XN  ((size_t)M_ * D_)     // 4,194,304
#define WN  ((size_t)D_ * D_)     // 1,048,576

// ---------------- scratch (device globals; no runtime allocation) ----------
__device__ uint32_t g_xt[XN];          // x as tf32 bits
__device__ uint32_t g_wt[4 * WN];      // wq,wk,wv,wo as tf32 bits
__device__ uint32_t g_q[XN];           // [B,H,S,hd] tf32 bits, pre-scaled 1/8
__device__ uint32_t g_k[XN];           // [B,H,S,hd] tf32 bits
__device__ uint32_t g_v[XN];           // [B,H,S,hd] tf32 bits
__device__ uint32_t g_attn[XN];        // [B,S,D] tf32 bits

// ======================= helpers ===========================================
__device__ __forceinline__ uint32_t smem_u32(const void* p) {
    uint32_t a;
    asm("{ .reg .u64 t; cvta.to.shared.u64 t, %1; cvt.u32.u64 %0, t; }"
        : "=r"(a) : "l"(p));
    return a;
}
__device__ __forceinline__ uint32_t f2tf32(float f) {
    uint32_t r;
    asm("cvt.rna.tf32.f32 %0, %1;" : "=r"(r) : "f"(f));
    return r;
}
#define CP_ASYNC16(dst, src) \
    asm volatile("cp.async.cg.shared.global [%0], [%1], 16;" \
                 :: "r"(dst), "l"(src) : "memory")
#define CP_COMMIT() asm volatile("cp.async.commit_group;" ::: "memory")
#define CP_WAIT0()  asm volatile("cp.async.wait_group 0;" ::: "memory")
#define CP_WAIT1()  asm volatile("cp.async.wait_group 1;" ::: "memory")

__device__ __forceinline__ void mma_tf32(float* c, uint32_t a0, uint32_t a1,
                                         uint32_t a2, uint32_t a3,
                                         uint32_t b0, uint32_t b1) {
    asm volatile(
        "mma.sync.aligned.m16n8k8.row.col.f32.tf32.tf32.f32 "
        "{%0,%1,%2,%3}, {%4,%5,%6,%7}, {%8,%9}, {%0,%1,%2,%3};"
        : "+f"(c[0]), "+f"(c[1]), "+f"(c[2]), "+f"(c[3])
        : "r"(a0), "r"(a1), "r"(a2), "r"(a3), "r"(b0), "r"(b1));
}

// ======================= prep: fp32 -> tf32 bits ===========================
// x (4M) then wq,wk,wv,wo (1M each), float4-granular grid-stride.
__global__ void __launch_bounds__(256)
prep_kernel(const float* __restrict__ x,
            const float* __restrict__ wq, const float* __restrict__ wk,
            const float* __restrict__ wv, const float* __restrict__ wo)
{
    const size_t i4 = (size_t)blockIdx.x * 256 + threadIdx.x;   // float4 index
    const size_t NT4 = (XN + 4 * WN) / 4;                       // 2,097,152
    if (i4 >= NT4) return;
    const size_t e = i4 * 4;
    const float* src;
    uint32_t* dst;
    if (e < XN)               { src = x  + e;            dst = g_xt + e; }
    else if (e < XN + WN)     { src = wq + (e - XN);     dst = g_wt + (e - XN); }
    else if (e < XN + 2 * WN) { src = wk + (e - XN - WN);     dst = g_wt + WN     + (e - XN - WN); }
    else if (e < XN + 3 * WN) { src = wv + (e - XN - 2 * WN); dst = g_wt + 2 * WN + (e - XN - 2 * WN); }
    else                      { src = wo + (e - XN - 3 * WN); dst = g_wt + 3 * WN + (e - XN - 3 * WN); }
    float4 v = *(const float4*)src;
    uint4 o;
    o.x = f2tf32(v.x); o.y = f2tf32(v.y);
    o.z = f2tf32(v.z); o.w = f2tf32(v.w);
    *(uint4*)dst = o;
}

// ======================= tf32 mma.sync GEMM (no in-loop cvt) ===============
// CTA 128x128, 8 warps (2m x 4n), warp tile m64 x n32, cp.async 2-stage.
#define GA_STRIDE 36
#define GB_STRIDE 136
#define GA_BYTES (128 * GA_STRIDE * 4)
#define GB_BYTES (32 * GB_STRIDE * 4)
#define GSTAGE   (GA_BYTES + GB_BYTES)
#define GA_OFF(s) ((s) * GSTAGE)
#define GB_OFF(s) ((s) * GSTAGE + GA_BYTES)
#define G_SMEM    (2 * GSTAGE)
#define G_NC      (D_ / 32)

template <int MODE>
__global__ void __launch_bounds__(256)
gemm_tc(const float* __restrict__ bias0,
        const float* __restrict__ bias1,
        const float* __restrict__ bias2,
        float* __restrict__ Cout)
{
    extern __shared__ char smc[];
    const uint32_t smb = smem_u32(smc);

    const uint32_t* W;
    const float* bias;
    uint32_t* dstq = nullptr;
    int zid = 0;
    if (MODE == 0) {
        zid = blockIdx.z;
        if (zid == 0)      { W = g_wt;          bias = bias0; dstq = g_q; }
        else if (zid == 1) { W = g_wt + WN;     bias = bias1; dstq = g_k; }
        else               { W = g_wt + 2 * WN; bias = bias2; dstq = g_v; }
    } else {
        W = g_wt + 3 * WN; bias = bias0;
    }
    const uint32_t* Ab = (MODE == 0) ? g_xt : g_attn;

    const int tid    = threadIdx.x;
    const int lid    = tid & 31;
    const int wid    = tid >> 5;
    const int warp_m = wid >> 2;
    const int warp_n = wid & 3;
    const int g      = lid >> 2;
    const int qq     = lid & 3;
    const int m0     = blockIdx.y * 128;
    const int n0     = blockIdx.x * 128;
    const int rb     = warp_m * 64;
    const int cb     = warp_n * 32;

    float acc[4][4][4];
#pragma unroll
    for (int mt = 0; mt < 4; mt++)
#pragma unroll
        for (int nt = 0; nt < 4; nt++)
#pragma unroll
            for (int e = 0; e < 4; e++) acc[mt][nt][e] = 0.f;

    auto load_chunk = [&](int c, int s) {
        const int k0 = c * 32;
        const uint32_t sa = smb + GA_OFF(s);
        const uint32_t sb = smb + GB_OFF(s);
#pragma unroll
        for (int i = 0; i < 4; i++) {
            const int e   = tid + i * 256;
            const int row = e >> 3;
            const int c4  = (e & 7) * 4;
            CP_ASYNC16(sa + (uint32_t)(row * GA_STRIDE + c4) * 4,
                       Ab + (size_t)(m0 + row) * D_ + k0 + c4);
        }
#pragma unroll
        for (int i = 0; i < 4; i++) {
            const int e  = tid + i * 256;
            const int kk = e >> 5;
            const int n4 = (e & 31) * 4;
            CP_ASYNC16(sb + (uint32_t)(kk * GB_STRIDE + n4) * 4,
                       W + (size_t)(k0 + kk) * D_ + n0 + n4);
        }
        CP_COMMIT();
    };

    load_chunk(0, 0);

#pragma unroll 1
    for (int c = 0; c < G_NC; c++) {
        const int s = c & 1;
        if (c + 1 < G_NC) {
            load_chunk(c + 1, s ^ 1);
            CP_WAIT1();
        } else {
            CP_WAIT0();
        }
        __syncthreads();

        const uint32_t (*As)[GA_STRIDE] = (const uint32_t(*)[GA_STRIDE])(smc + GA_OFF(s));
        const uint32_t (*Bs)[GB_STRIDE] = (const uint32_t(*)[GB_STRIDE])(smc + GB_OFF(s));

#pragma unroll
        for (int k8 = 0; k8 < 4; k8++) {
            const int k0 = k8 * 8;
            uint32_t bf[4][2];
#pragma unroll
            for (int nt = 0; nt < 4; nt++) {
                bf[nt][0] = Bs[k0 + qq][cb + nt * 8 + g];
                bf[nt][1] = Bs[k0 + qq + 4][cb + nt * 8 + g];
            }
#pragma unroll
            for (int mt = 0; mt < 4; mt++) {
                const int r = rb + mt * 16 + g;
                uint32_t a0 = As[r][k0 + qq];
                uint32_t a1 = As[r + 8][k0 + qq];
                uint32_t a2 = As[r][k0 + qq + 4];
                uint32_t a3 = As[r + 8][k0 + qq + 4];
#pragma unroll
                for (int nt = 0; nt < 4; nt++)
                    mma_tf32(acc[mt][nt], a0, a1, a2, a3, bf[nt][0], bf[nt][1]);
            }
        }
        __syncthreads();
    }

    // ---- epilogue ----
    const float qscale = (MODE == 0 && zid == 0) ? 0.125f : 1.f;
#pragma unroll
    for (int mt = 0; mt < 4; mt++) {
#pragma unroll
        for (int half = 0; half < 2; half++) {
            const int m  = m0 + rb + mt * 16 + half * 8 + g;
            const int bb = m / S_;
            const int ss = m % S_;
#pragma unroll
            for (int nt = 0; nt < 4; nt++) {
                const int gc = n0 + cb + nt * 8 + 2 * qq;
                float vx = acc[mt][nt][half * 2 + 0] + bias[gc];
                float vy = acc[mt][nt][half * 2 + 1] + bias[gc + 1];
                if (MODE == 0) {
                    const int h = gc >> 6;
                    const int d = gc & 63;
                    uint2 o = make_uint2(f2tf32(vx * qscale), f2tf32(vy * qscale));
                    *(uint2*)(dstq + ((((size_t)bb * H_ + h) * S_ + ss) << 6) + d) = o;
                } else {
                    *(float2*)(Cout + (size_t)m * D_ + gc) = make_float2(vx, vy);
                }
            }
        }
    }
}

// ======================= tf32 mma.sync flash attention =====================
// Same structure as R13 but Q/K/V arrive as tf32 bits: zero cvt in QK/PV loops.
#define AQ_OFF 0
#define AP_OFF (128 * 68)
#define AK_OFF(s) (2 * 128 * 68 + (s) * 64 * 68)
#define AV_OFF(s) (2 * 128 * 68 + 2 * 64 * 68 + (s) * 64 * 72)
#define A_SMEM_FLOATS (2 * 128 * 68 + 2 * 64 * 68 + 2 * 64 * 72)  // 35328

__global__ void __launch_bounds__(256)
attn_kernel()
{
    extern __shared__ uint32_t sm[];
    const uint32_t smb = smem_u32(sm);
    uint32_t* QS = sm + AQ_OFF;   // [128][68] tf32 bits (pre-scaled)
    uint32_t* PS = sm + AP_OFF;   // [128][68] tf32 bits

    const int qt  = blockIdx.x;
    const int bh  = blockIdx.y;
    const int b   = bh >> 4;
    const int h   = bh & 15;
    const int tid = threadIdx.x;
    const int lid = tid & 31;
    const int wid = tid >> 5;
    const int g   = lid >> 2;
    const int qq  = lid & 3;
    const int q0  = qt * 128;
    const int rw  = wid * 16 + g;

    const uint32_t* Qp = g_q + (size_t)bh * S_ * HD_;
    const uint32_t* Kp = g_k + (size_t)bh * S_ * HD_;
    const uint32_t* Vp = g_v + (size_t)bh * S_ * HD_;

    // ---- load Q once (already scaled + converted) ----
#pragma unroll
    for (int i = 0; i < 8; i++) {
        const int e   = tid + i * 256;
        const int row = e >> 4;
        const int c4  = (e & 15) * 4;
        uint4 qv = *(const uint4*)(Qp + (size_t)(q0 + row) * HD_ + c4);
        *(uint4*)(QS + row * 68 + c4) = qv;
    }

    auto load_kv = [&](int t, int s) {
        const int k0 = t * 64;
        const uint32_t ks = smb + (AK_OFF(s)) * 4;
        const uint32_t vs = smb + (AV_OFF(s)) * 4;
#pragma unroll
        for (int i = 0; i < 4; i++) {
            const int e   = tid + i * 256;
            const int row = e >> 4;
            const int c4  = (e & 15) * 4;
            CP_ASYNC16(ks + (uint32_t)(row * 68 + c4) * 4,
                       Kp + (size_t)(k0 + row) * HD_ + c4);
            CP_ASYNC16(vs + (uint32_t)(row * 72 + c4) * 4,
                       Vp + (size_t)(k0 + row) * HD_ + c4);
        }
        CP_COMMIT();
    };

    float m0 = -1e30f, m1 = -1e30f, l0 = 0.f, l1 = 0.f;
    float O[8][4];
#pragma unroll
    for (int nt = 0; nt < 8; nt++)
#pragma unroll
        for (int e = 0; e < 4; e++) O[nt][e] = 0.f;

    load_kv(0, 0);

    const int ntiles = 2 * qt + 2;   // causal
#pragma unroll 1
    for (int t = 0; t < ntiles; t++) {
        const int s = t & 1;
        if (t + 1 < ntiles) {
            load_kv(t + 1, s ^ 1);
            CP_WAIT1();
        } else {
            CP_WAIT0();
        }
        __syncthreads();

        const uint32_t (*KS)[68] = (const uint32_t(*)[68])(sm + AK_OFF(s));
        const uint32_t (*VS)[72] = (const uint32_t(*)[72])(sm + AV_OFF(s));

        // ---- S = Q K^T ----
        float sc[8][4];
#pragma unroll
        for (int nt = 0; nt < 8; nt++)
#pragma unroll
            for (int e = 0; e < 4; e++) sc[nt][e] = 0.f;

#pragma unroll
        for (int kk = 0; kk < 8; kk++) {
            const int k = kk * 8 + qq;
            uint32_t a0 = QS[rw * 68 + k];
            uint32_t a1 = QS[(rw + 8) * 68 + k];
            uint32_t a2 = QS[rw * 68 + k + 4];
            uint32_t a3 = QS[(rw + 8) * 68 + k + 4];
#pragma unroll
            for (int nt = 0; nt < 8; nt++) {
                uint32_t b0 = KS[nt * 8 + g][k];
                uint32_t b1 = KS[nt * 8 + g][k + 4];
                mma_tf32(sc[nt], a0, a1, a2, a3, b0, b1);
            }
        }

        // ---- causal mask ----
        const int k0g = t * 64;
        if (t + 2 >= ntiles) {
            const int qi0 = q0 + rw;
            const int qi1 = qi0 + 8;
#pragma unroll
            for (int nt = 0; nt < 8; nt++) {
                const int c0 = k0g + nt * 8 + 2 * qq;
                if (c0 > qi0)     sc[nt][0] = -1e30f;
                if (c0 + 1 > qi0) sc[nt][1] = -1e30f;
                if (c0 > qi1)     sc[nt][2] = -1e30f;
                if (c0 + 1 > qi1) sc[nt][3] = -1e30f;
            }
        }

        // ---- online softmax ----
        float mx0 = -1e30f, mx1 = -1e30f;
#pragma unroll
        for (int nt = 0; nt < 8; nt++) {
            mx0 = fmaxf(mx0, fmaxf(sc[nt][0], sc[nt][1]));
            mx1 = fmaxf(mx1, fmaxf(sc[nt][2], sc[nt][3]));
        }
        mx0 = fmaxf(mx0, __shfl_xor_sync(0xffffffffu, mx0, 1));
        mx0 = fmaxf(mx0, __shfl_xor_sync(0xffffffffu, mx0, 2));
        mx1 = fmaxf(mx1, __shfl_xor_sync(0xffffffffu, mx1, 1));
        mx1 = fmaxf(mx1, __shfl_xor_sync(0xffffffffu, mx1, 2));

        const float mn0 = fmaxf(m0, mx0);
        const float mn1 = fmaxf(m1, mx1);
        const float al0 = __expf(m0 - mn0);
        const float al1 = __expf(m1 - mn1);

        float ls0 = 0.f, ls1 = 0.f;
#pragma unroll
        for (int nt = 0; nt < 8; nt++) {
            float p00 = __expf(sc[nt][0] - mn0);
            float p01 = __expf(sc[nt][1] - mn0);
            float p10 = __expf(sc[nt][2] - mn1);
            float p11 = __expf(sc[nt][3] - mn1);
            ls0 += p00 + p01;
            ls1 += p10 + p11;
            *(uint2*)(PS + rw * 68 + nt * 8 + 2 * qq) =
                make_uint2(f2tf32(p00), f2tf32(p01));
            *(uint2*)(PS + (rw + 8) * 68 + nt * 8 + 2 * qq) =
                make_uint2(f2tf32(p10), f2tf32(p11));
        }
        ls0 += __shfl_xor_sync(0xffffffffu, ls0, 1);
        ls0 += __shfl_xor_sync(0xffffffffu, ls0, 2);
        ls1 += __shfl_xor_sync(0xffffffffu, ls1, 1);
        ls1 += __shfl_xor_sync(0xffffffffu, ls1, 2);
        l0 = l0 * al0 + ls0;
        l1 = l1 * al1 + ls1;
        m0 = mn0; m1 = mn1;
#pragma unroll
        for (int nt = 0; nt < 8; nt++) {
            O[nt][0] *= al0; O[nt][1] *= al0;
            O[nt][2] *= al1; O[nt][3] *= al1;
        }
        __syncwarp();   // PS rows warp-private

        // ---- O += P V ----
#pragma unroll
        for (int kk = 0; kk < 8; kk++) {
            const int k = kk * 8 + qq;
            uint32_t a0 = PS[rw * 68 + k];
            uint32_t a1 = PS[(rw + 8) * 68 + k];
            uint32_t a2 = PS[rw * 68 + k + 4];
            uint32_t a3 = PS[(rw + 8) * 68 + k + 4];
#pragma unroll
            for (int nt = 0; nt < 8; nt++) {
                uint32_t b0 = VS[kk * 8 + qq][nt * 8 + g];
                uint32_t b1 = VS[kk * 8 + qq + 4][nt * 8 + g];
                mma_tf32(O[nt], a0, a1, a2, a3, b0, b1);
            }
        }
        __syncthreads();
    }

    // ---- finalize: /l, write tf32 bits to g_attn [B,S,D] ----
    const float inv0 = 1.f / l0;
    const float inv1 = 1.f / l1;
    const int qg0 = q0 + rw;
    uint32_t* d0 = g_attn + ((size_t)(b * S_ + qg0)) * D_ + h * HD_;
    uint32_t* d1 = d0 + (size_t)8 * D_;
#pragma unroll
    for (int nt = 0; nt < 8; nt++) {
        const int col = nt * 8 + 2 * qq;
        *(uint2*)(d0 + col) =
            make_uint2(f2tf32(O[nt][0] * inv0), f2tf32(O[nt][1] * inv0));
        *(uint2*)(d1 + col) =
            make_uint2(f2tf32(O[nt][2] * inv1), f2tf32(O[nt][3] * inv1));
    }
}

// ---------------------------------------------------------------------------
extern "C" void kernel_launch(void* const* d_in, const int* in_sizes, int n_in,
                              void* d_out, int out_size)
{
    const float* x  = (const float*)d_in[0];
    const float* wq = (const float*)d_in[1];
    const float* bq = (const float*)d_in[2];
    const float* wk = (const float*)d_in[3];
    const float* bk = (const float*)d_in[4];
    const float* wv = (const float*)d_in[5];
    const float* bv = (const float*)d_in[6];
    const float* wo = (const float*)d_in[7];
    const float* bo = (const float*)d_in[8];
    float* out = (float*)d_out;

    cudaFuncSetAttribute(attn_kernel,
                         cudaFuncAttributeMaxDynamicSharedMemorySize,
                         A_SMEM_FLOATS * (int)sizeof(uint32_t));
    cudaFuncSetAttribute(gemm_tc<0>,
                         cudaFuncAttributeMaxDynamicSharedMemorySize, G_SMEM);
    cudaFuncSetAttribute(gemm_tc<1>,
                         cudaFuncAttributeMaxDynamicSharedMemorySize, G_SMEM);

    // 0) convert x + weights to tf32 bits
    const int prep_blocks = (int)(((XN + 4 * WN) / 4 + 255) / 256);
    prep_kernel<<<prep_blocks, 256>>>(x, wq, wk, wv, wo);

    // 1) fused QKV projections -> g_q/g_k/g_v (tf32 bits, [B,H,S,hd])
    dim3 gq(D_ / 128, M_ / 128, 3);
    gemm_tc<0><<<gq, 256, G_SMEM>>>(bq, bk, bv, nullptr);

    // 2) causal flash attention -> g_attn (tf32 bits, [B,S,D])
    dim3 ga(S_ / 128, B_ * H_);
    attn_kernel<<<ga, 256, A_SMEM_FLOATS * (int)sizeof(uint32_t)>>>();

    // 3) output projection -> d_out (fp32)
    dim3 go(D_ / 128, M_ / 128, 1);
    gemm_tc<1><<<go, 256, G_SMEM>>>(bo, nullptr, nullptr, out);
}

// round 16
// speedup vs baseline: 3.6693x; 1.0140x over previous
#include <cuda_runtime.h>
#include <math.h>
#include <stdint.h>

#define B_  2
#define S_  2048
#define D_  1024
#define H_  16
#define HD_ 64
#define M_  (B_ * S_)   // 4096
#define XN  ((size_t)M_ * D_)     // 4,194,304
#define WN  ((size_t)D_ * D_)     // 1,048,576

// ---------------- scratch (device globals; no runtime allocation) ----------
__device__ uint32_t g_xt[XN];          // x as tf32 bits
__device__ uint32_t g_wt[4 * WN];      // wq,wk,wv,wo as tf32 bits
__device__ uint32_t g_q[XN];           // [B,H,S,hd] tf32 bits, pre-scaled 1/8
__device__ uint32_t g_k[XN];           // [B,H,S,hd] tf32 bits
__device__ uint32_t g_v[XN];           // [B,H,S,hd] tf32 bits
__device__ uint32_t g_attn[XN];        // [B,S,D] tf32 bits

// ======================= helpers ===========================================
__device__ __forceinline__ uint32_t smem_u32(const void* p) {
    uint32_t a;
    asm("{ .reg .u64 t; cvta.to.shared.u64 t, %1; cvt.u32.u64 %0, t; }"
        : "=r"(a) : "l"(p));
    return a;
}
__device__ __forceinline__ uint32_t f2tf32(float f) {
    uint32_t r;
    asm("cvt.rna.tf32.f32 %0, %1;" : "=r"(r) : "f"(f));
    return r;
}
#define CP_ASYNC16(dst, src) \
    asm volatile("cp.async.cg.shared.global [%0], [%1], 16;" \
                 :: "r"(dst), "l"(src) : "memory")
#define CP_COMMIT() asm volatile("cp.async.commit_group;" ::: "memory")
#define CP_WAIT0()  asm volatile("cp.async.wait_group 0;" ::: "memory")
#define CP_WAIT1()  asm volatile("cp.async.wait_group 1;" ::: "memory")
#define CP_WAIT2()  asm volatile("cp.async.wait_group 2;" ::: "memory")

__device__ __forceinline__ void mma_tf32(float* c, uint32_t a0, uint32_t a1,
                                         uint32_t a2, uint32_t a3,
                                         uint32_t b0, uint32_t b1) {
    asm volatile(
        "mma.sync.aligned.m16n8k8.row.col.f32.tf32.tf32.f32 "
        "{%0,%1,%2,%3}, {%4,%5,%6,%7}, {%8,%9}, {%0,%1,%2,%3};"
        : "+f"(c[0]), "+f"(c[1]), "+f"(c[2]), "+f"(c[3])
        : "r"(a0), "r"(a1), "r"(a2), "r"(a3), "r"(b0), "r"(b1));
}

// ======================= prep: fp32 -> tf32 bits ===========================
__global__ void __launch_bounds__(256)
prep_kernel(const float* __restrict__ x,
            const float* __restrict__ wq, const float* __restrict__ wk,
            const float* __restrict__ wv, const float* __restrict__ wo)
{
    const size_t i4 = (size_t)blockIdx.x * 256 + threadIdx.x;
    const size_t NT4 = (XN + 4 * WN) / 4;
    if (i4 >= NT4) return;
    const size_t e = i4 * 4;
    const float* src;
    uint32_t* dst;
    if (e < XN)               { src = x  + e;            dst = g_xt + e; }
    else if (e < XN + WN)     { src = wq + (e - XN);     dst = g_wt + (e - XN); }
    else if (e < XN + 2 * WN) { src = wk + (e - XN - WN);     dst = g_wt + WN     + (e - XN - WN); }
    else if (e < XN + 3 * WN) { src = wv + (e - XN - 2 * WN); dst = g_wt + 2 * WN + (e - XN - 2 * WN); }
    else                      { src = wo + (e - XN - 3 * WN); dst = g_wt + 3 * WN + (e - XN - 3 * WN); }
    float4 v = *(const float4*)src;
    uint4 o;
    o.x = f2tf32(v.x); o.y = f2tf32(v.y);
    o.z = f2tf32(v.z); o.w = f2tf32(v.w);
    *(uint4*)dst = o;
}

// ======================= tf32 mma.sync GEMM (3-stage cp.async) =============
#define GA_STRIDE 36
#define GB_STRIDE 136
#define GA_BYTES (128 * GA_STRIDE * 4)
#define GB_BYTES (32 * GB_STRIDE * 4)
#define GSTAGE   (GA_BYTES + GB_BYTES)
#define GA_OFF(s) ((s) * GSTAGE)
#define GB_OFF(s) ((s) * GSTAGE + GA_BYTES)
#define G_SMEM    (3 * GSTAGE)                 // 107520 B, 2 CTAs/SM
#define G_NC      (D_ / 32)

template <int MODE>
__global__ void __launch_bounds__(256, 2)
gemm_tc(const float* __restrict__ bias0,
        const float* __restrict__ bias1,
        const float* __restrict__ bias2,
        float* __restrict__ Cout)
{
    extern __shared__ char smc[];
    const uint32_t smb = smem_u32(smc);

    const uint32_t* W;
    const float* bias;
    uint32_t* dstq = nullptr;
    int zid = 0;
    if (MODE == 0) {
        zid = blockIdx.z;
        if (zid == 0)      { W = g_wt;          bias = bias0; dstq = g_q; }
        else if (zid == 1) { W = g_wt + WN;     bias = bias1; dstq = g_k; }
        else               { W = g_wt + 2 * WN; bias = bias2; dstq = g_v; }
    } else {
        W = g_wt + 3 * WN; bias = bias0;
    }
    const uint32_t* Ab = (MODE == 0) ? g_xt : g_attn;

    const int tid    = threadIdx.x;
    const int lid    = tid & 31;
    const int wid    = tid >> 5;
    const int warp_m = wid >> 2;
    const int warp_n = wid & 3;
    const int g      = lid >> 2;
    const int qq     = lid & 3;
    const int m0     = blockIdx.y * 128;
    const int n0     = blockIdx.x * 128;
    const int rb     = warp_m * 64;
    const int cb     = warp_n * 32;

    float acc[4][4][4];
#pragma unroll
    for (int mt = 0; mt < 4; mt++)
#pragma unroll
        for (int nt = 0; nt < 4; nt++)
#pragma unroll
            for (int e = 0; e < 4; e++) acc[mt][nt][e] = 0.f;

    auto load_chunk = [&](int c, int s) {
        const int k0 = c * 32;
        const uint32_t sa = smb + GA_OFF(s);
        const uint32_t sb = smb + GB_OFF(s);
#pragma unroll
        for (int i = 0; i < 4; i++) {
            const int e   = tid + i * 256;
            const int row = e >> 3;
            const int c4  = (e & 7) * 4;
            CP_ASYNC16(sa + (uint32_t)(row * GA_STRIDE + c4) * 4,
                       Ab + (size_t)(m0 + row) * D_ + k0 + c4);
        }
#pragma unroll
        for (int i = 0; i < 4; i++) {
            const int e  = tid + i * 256;
            const int kk = e >> 5;
            const int n4 = (e & 31) * 4;
            CP_ASYNC16(sb + (uint32_t)(kk * GB_STRIDE + n4) * 4,
                       W + (size_t)(k0 + kk) * D_ + n0 + n4);
        }
        CP_COMMIT();
    };

    load_chunk(0, 0);
    load_chunk(1, 1);

#pragma unroll 1
    for (int c = 0; c < G_NC; c++) {
        // uniform one commit per iter: pending groups after this = c+1, c+2
        if (c + 2 < G_NC) load_chunk(c + 2, (c + 2) % 3);
        else              CP_COMMIT();
        CP_WAIT2();                 // stage c complete
        __syncthreads();

        const int s = c % 3;
        const uint32_t (*As)[GA_STRIDE] = (const uint32_t(*)[GA_STRIDE])(smc + GA_OFF(s));
        const uint32_t (*Bs)[GB_STRIDE] = (const uint32_t(*)[GB_STRIDE])(smc + GB_OFF(s));

#pragma unroll
        for (int k8 = 0; k8 < 4; k8++) {
            const int k0 = k8 * 8;
            uint32_t bf[4][2];
#pragma unroll
            for (int nt = 0; nt < 4; nt++) {
                bf[nt][0] = Bs[k0 + qq][cb + nt * 8 + g];
                bf[nt][1] = Bs[k0 + qq + 4][cb + nt * 8 + g];
            }
#pragma unroll
            for (int mt = 0; mt < 4; mt++) {
                const int r = rb + mt * 16 + g;
                uint32_t a0 = As[r][k0 + qq];
                uint32_t a1 = As[r + 8][k0 + qq];
                uint32_t a2 = As[r][k0 + qq + 4];
                uint32_t a3 = As[r + 8][k0 + qq + 4];
#pragma unroll
                for (int nt = 0; nt < 4; nt++)
                    mma_tf32(acc[mt][nt], a0, a1, a2, a3, bf[nt][0], bf[nt][1]);
            }
        }
        __syncthreads();            // stage s free for reuse at iter c+1
    }

    // ---- epilogue ----
    const float qscale = (MODE == 0 && zid == 0) ? 0.125f : 1.f;
#pragma unroll
    for (int mt = 0; mt < 4; mt++) {
#pragma unroll
        for (int half = 0; half < 2; half++) {
            const int m  = m0 + rb + mt * 16 + half * 8 + g;
            const int bb = m / S_;
            const int ss = m % S_;
#pragma unroll
            for (int nt = 0; nt < 4; nt++) {
                const int gc = n0 + cb + nt * 8 + 2 * qq;
                float vx = acc[mt][nt][half * 2 + 0] + bias[gc];
                float vy = acc[mt][nt][half * 2 + 1] + bias[gc + 1];
                if (MODE == 0) {
                    const int h = gc >> 6;
                    const int d = gc & 63;
                    uint2 o = make_uint2(f2tf32(vx * qscale), f2tf32(vy * qscale));
                    *(uint2*)(dstq + ((((size_t)bb * H_ + h) * S_ + ss) << 6) + d) = o;
                } else {
                    *(float2*)(Cout + (size_t)m * D_ + gc) = make_float2(vx, vy);
                }
            }
        }
    }
}

// ======================= tf32 mma.sync flash attention =====================
// R16: Q fragments live in registers (staged once through the P buffer);
// smem drops 141 -> 106.5 KB => 2 CTAs/SM. Longest-first qt order.
#define AP_OFF 0                                  // [128][68]: Q staging, then P
#define AK_OFF(s) (128 * 68 + (s) * 64 * 68)
#define AV_OFF(s) (128 * 68 + 2 * 64 * 68 + (s) * 64 * 72)
#define A_SMEM_W  (128 * 68 + 2 * 64 * 68 + 2 * 64 * 72)   // 26624 words = 106496 B

__global__ void __launch_bounds__(256, 2)
attn_kernel()
{
    extern __shared__ uint32_t sm[];
    const uint32_t smb = smem_u32(sm);
    uint32_t* PS = sm + AP_OFF;

    const int qt  = (int)gridDim.x - 1 - (int)blockIdx.x;   // longest first
    const int bh  = blockIdx.y;
    const int b   = bh >> 4;
    const int h   = bh & 15;
    const int tid = threadIdx.x;
    const int lid = tid & 31;
    const int wid = tid >> 5;
    const int g   = lid >> 2;
    const int qq  = lid & 3;
    const int q0  = qt * 128;
    const int rw  = wid * 16 + g;

    const uint32_t* Qp = g_q + (size_t)bh * S_ * HD_;
    const uint32_t* Kp = g_k + (size_t)bh * S_ * HD_;
    const uint32_t* Vp = g_v + (size_t)bh * S_ * HD_;

    auto load_kv = [&](int t, int s) {
        const int k0 = t * 64;
        const uint32_t ks = smb + (AK_OFF(s)) * 4;
        const uint32_t vs = smb + (AV_OFF(s)) * 4;
#pragma unroll
        for (int i = 0; i < 4; i++) {
            const int e   = tid + i * 256;
            const int row = e >> 4;
            const int c4  = (e & 15) * 4;
            CP_ASYNC16(ks + (uint32_t)(row * 68 + c4) * 4,
                       Kp + (size_t)(k0 + row) * HD_ + c4);
            CP_ASYNC16(vs + (uint32_t)(row * 72 + c4) * 4,
                       Vp + (size_t)(k0 + row) * HD_ + c4);
        }
        CP_COMMIT();
    };

    // KV tile 0 in flight while Q is staged
    load_kv(0, 0);

    // ---- stage Q through PS, pull fragments to registers ----
#pragma unroll
    for (int i = 0; i < 8; i++) {
        const int e   = tid + i * 256;
        const int row = e >> 4;
        const int c4  = (e & 15) * 4;
        uint4 qv = *(const uint4*)(Qp + (size_t)(q0 + row) * HD_ + c4);
        *(uint4*)(PS + row * 68 + c4) = qv;
    }
    __syncthreads();
    uint32_t qa[8][4];
#pragma unroll
    for (int kk = 0; kk < 8; kk++) {
        const int k = kk * 8 + qq;
        qa[kk][0] = PS[rw * 68 + k];
        qa[kk][1] = PS[(rw + 8) * 68 + k];
        qa[kk][2] = PS[rw * 68 + k + 4];
        qa[kk][3] = PS[(rw + 8) * 68 + k + 4];
    }
    __syncthreads();   // all pulls done; PS free for P (rows warp-private)

    float m0 = -1e30f, m1 = -1e30f, l0 = 0.f, l1 = 0.f;
    float O[8][4];
#pragma unroll
    for (int nt = 0; nt < 8; nt++)
#pragma unroll
        for (int e = 0; e < 4; e++) O[nt][e] = 0.f;

    const int ntiles = 2 * qt + 2;   // causal
#pragma unroll 1
    for (int t = 0; t < ntiles; t++) {
        const int s = t & 1;
        if (t + 1 < ntiles) {
            load_kv(t + 1, s ^ 1);
            CP_WAIT1();
        } else {
            CP_WAIT0();
        }
        __syncthreads();

        const uint32_t (*KS)[68] = (const uint32_t(*)[68])(sm + AK_OFF(s));
        const uint32_t (*VS)[72] = (const uint32_t(*)[72])(sm + AV_OFF(s));

        // ---- S = Q K^T (Q from registers) ----
        float sc[8][4];
#pragma unroll
        for (int nt = 0; nt < 8; nt++)
#pragma unroll
            for (int e = 0; e < 4; e++) sc[nt][e] = 0.f;

#pragma unroll
        for (int kk = 0; kk < 8; kk++) {
            const int k = kk * 8 + qq;
#pragma unroll
            for (int nt = 0; nt < 8; nt++) {
                uint32_t b0 = KS[nt * 8 + g][k];
                uint32_t b1 = KS[nt * 8 + g][k + 4];
                mma_tf32(sc[nt], qa[kk][0], qa[kk][1], qa[kk][2], qa[kk][3],
                         b0, b1);
            }
        }

        // ---- causal mask ----
        const int k0g = t * 64;
        if (t + 2 >= ntiles) {
            const int qi0 = q0 + rw;
            const int qi1 = qi0 + 8;
#pragma unroll
            for (int nt = 0; nt < 8; nt++) {
                const int c0 = k0g + nt * 8 + 2 * qq;
                if (c0 > qi0)     sc[nt][0] = -1e30f;
                if (c0 + 1 > qi0) sc[nt][1] = -1e30f;
                if (c0 > qi1)     sc[nt][2] = -1e30f;
                if (c0 + 1 > qi1) sc[nt][3] = -1e30f;
            }
        }

        // ---- online softmax ----
        float mx0 = -1e30f, mx1 = -1e30f;
#pragma unroll
        for (int nt = 0; nt < 8; nt++) {
            mx0 = fmaxf(mx0, fmaxf(sc[nt][0], sc[nt][1]));
            mx1 = fmaxf(mx1, fmaxf(sc[nt][2], sc[nt][3]));
        }
        mx0 = fmaxf(mx0, __shfl_xor_sync(0xffffffffu, mx0, 1));
        mx0 = fmaxf(mx0, __shfl_xor_sync(0xffffffffu, mx0, 2));
        mx1 = fmaxf(mx1, __shfl_xor_sync(0xffffffffu, mx1, 1));
        mx1 = fmaxf(mx1, __shfl_xor_sync(0xffffffffu, mx1, 2));

        const float mn0 = fmaxf(m0, mx0);
        const float mn1 = fmaxf(m1, mx1);
        const float al0 = __expf(m0 - mn0);
        const float al1 = __expf(m1 - mn1);

        float ls0 = 0.f, ls1 = 0.f;
#pragma unroll
        for (int nt = 0; nt < 8; nt++) {
            float p00 = __expf(sc[nt][0] - mn0);
            float p01 = __expf(sc[nt][1] - mn0);
            float p10 = __expf(sc[nt][2] - mn1);
            float p11 = __expf(sc[nt][3] - mn1);
            ls0 += p00 + p01;
            ls1 += p10 + p11;
            *(uint2*)(PS + rw * 68 + nt * 8 + 2 * qq) =
                make_uint2(f2tf32(p00), f2tf32(p01));
            *(uint2*)(PS + (rw + 8) * 68 + nt * 8 + 2 * qq) =
                make_uint2(f2tf32(p10), f2tf32(p11));
        }
        ls0 += __shfl_xor_sync(0xffffffffu, ls0, 1);
        ls0 += __shfl_xor_sync(0xffffffffu, ls0, 2);
        ls1 += __shfl_xor_sync(0xffffffffu, ls1, 1);
        ls1 += __shfl_xor_sync(0xffffffffu, ls1, 2);
        l0 = l0 * al0 + ls0;
        l1 = l1 * al1 + ls1;
        m0 = mn0; m1 = mn1;
#pragma unroll
        for (int nt = 0; nt < 8; nt++) {
            O[nt][0] *= al0; O[nt][1] *= al0;
            O[nt][2] *= al1; O[nt][3] *= al1;
        }
        __syncwarp();   // PS rows warp-private: order STS -> LDS

        // ---- O += P V ----
#pragma unroll
        for (int kk = 0; kk < 8; kk++) {
            const int k = kk * 8 + qq;
            uint32_t a0 = PS[rw * 68 + k];
            uint32_t a1 = PS[(rw + 8) * 68 + k];
            uint32_t a2 = PS[rw * 68 + k + 4];
            uint32_t a3 = PS[(rw + 8) * 68 + k + 4];
#pragma unroll
            for (int nt = 0; nt < 8; nt++) {
                uint32_t b0 = VS[kk * 8 + qq][nt * 8 + g];
                uint32_t b1 = VS[kk * 8 + qq + 4][nt * 8 + g];
                mma_tf32(O[nt], a0, a1, a2, a3, b0, b1);
            }
        }
        __syncthreads();   // KV stage + PS reuse safe
    }

    // ---- finalize: /l, write tf32 bits to g_attn [B,S,D] ----
    const float inv0 = 1.f / l0;
    const float inv1 = 1.f / l1;
    const int qg0 = q0 + rw;
    uint32_t* d0 = g_attn + ((size_t)(b * S_ + qg0)) * D_ + h * HD_;
    uint32_t* d1 = d0 + (size_t)8 * D_;
#pragma unroll
    for (int nt = 0; nt < 8; nt++) {
        const int col = nt * 8 + 2 * qq;
        *(uint2*)(d0 + col) =
            make_uint2(f2tf32(O[nt][0] * inv0), f2tf32(O[nt][1] * inv0));
        *(uint2*)(d1 + col) =
            make_uint2(f2tf32(O[nt][2] * inv1), f2tf32(O[nt][3] * inv1));
    }
}

// ---------------------------------------------------------------------------
extern "C" void kernel_launch(void* const* d_in, const int* in_sizes, int n_in,
                              void* d_out, int out_size)
{
    const float* x  = (const float*)d_in[0];
    const float* wq = (const float*)d_in[1];
    const float* bq = (const float*)d_in[2];
    const float* wk = (const float*)d_in[3];
    const float* bk = (const float*)d_in[4];
    const float* wv = (const float*)d_in[5];
    const float* bv = (const float*)d_in[6];
    const float* wo = (const float*)d_in[7];
    const float* bo = (const float*)d_in[8];
    float* out = (float*)d_out;

    cudaFuncSetAttribute(attn_kernel,
                         cudaFuncAttributeMaxDynamicSharedMemorySize,
                         A_SMEM_W * (int)sizeof(uint32_t));
    cudaFuncSetAttribute(gemm_tc<0>,
                         cudaFuncAttributeMaxDynamicSharedMemorySize, G_SMEM);
    cudaFuncSetAttribute(gemm_tc<1>,
                         cudaFuncAttributeMaxDynamicSharedMemorySize, G_SMEM);

    // 0) convert x + weights to tf32 bits
    const int prep_blocks = (int)(((XN + 4 * WN) / 4 + 255) / 256);
    prep_kernel<<<prep_blocks, 256>>>(x, wq, wk, wv, wo);

    // 1) fused QKV projections -> g_q/g_k/g_v (tf32 bits, [B,H,S,hd])
    dim3 gq(D_ / 128, M_ / 128, 3);
    gemm_tc<0><<<gq, 256, G_SMEM>>>(bq, bk, bv, nullptr);

    // 2) causal flash attention -> g_attn (tf32 bits, [B,S,D])
    dim3 ga(S_ / 128, B_ * H_);
    attn_kernel<<<ga, 256, A_SMEM_W * (int)sizeof(uint32_t)>>>();

    // 3) output projection -> d_out (fp32)
    dim3 go(D_ / 128, M_ / 128, 1);
    gemm_tc<1><<<go, 256, G_SMEM>>>(bo, nullptr, nullptr, out);
}

// round 17
// speedup vs baseline: 3.6981x; 1.0078x over previous
#include <cuda_runtime.h>
#include <math.h>
#include <stdint.h>

#define B_  2
#define S_  2048
#define D_  1024
#define H_  16
#define HD_ 64
#define M_  (B_ * S_)   // 4096
#define XN  ((size_t)M_ * D_)     // 4,194,304
#define WN  ((size_t)D_ * D_)     // 1,048,576

// ---------------- scratch (device globals; no runtime allocation) ----------
__device__ uint32_t g_xt[XN];          // x as tf32 bits
__device__ uint32_t g_wt[4 * WN];      // wq,wk,wv,wo as tf32 bits
__device__ uint32_t g_q[XN];           // [B,H,S,hd] tf32 bits, pre-scaled 1/8
__device__ uint32_t g_k[XN];           // [B,H,S,hd] tf32 bits
__device__ uint32_t g_v[XN];           // [B,H,S,hd] tf32 bits
__device__ uint32_t g_attn[XN];        // [B,S,D] tf32 bits

// ======================= helpers ===========================================
__device__ __forceinline__ uint32_t smem_u32(const void* p) {
    uint32_t a;
    asm("{ .reg .u64 t; cvta.to.shared.u64 t, %1; cvt.u32.u64 %0, t; }"
        : "=r"(a) : "l"(p));
    return a;
}
__device__ __forceinline__ uint32_t f2tf32(float f) {
    uint32_t r;
    asm("cvt.rna.tf32.f32 %0, %1;" : "=r"(r) : "f"(f));
    return r;
}
#define CP_ASYNC16(dst, src) \
    asm volatile("cp.async.cg.shared.global [%0], [%1], 16;" \
                 :: "r"(dst), "l"(src) : "memory")
#define CP_COMMIT() asm volatile("cp.async.commit_group;" ::: "memory")
#define CP_WAIT0()  asm volatile("cp.async.wait_group 0;" ::: "memory")
#define CP_WAIT1()  asm volatile("cp.async.wait_group 1;" ::: "memory")

__device__ __forceinline__ void mma_tf32(float* c, uint32_t a0, uint32_t a1,
                                         uint32_t a2, uint32_t a3,
                                         uint32_t b0, uint32_t b1) {
    asm volatile(
        "mma.sync.aligned.m16n8k8.row.col.f32.tf32.tf32.f32 "
        "{%0,%1,%2,%3}, {%4,%5,%6,%7}, {%8,%9}, {%0,%1,%2,%3};"
        : "+f"(c[0]), "+f"(c[1]), "+f"(c[2]), "+f"(c[3])
        : "r"(a0), "r"(a1), "r"(a2), "r"(a3), "r"(b0), "r"(b1));
}

// ======================= prep: fp32 -> tf32 bits ===========================
__global__ void __launch_bounds__(256)
prep_kernel(const float* __restrict__ x,
            const float* __restrict__ wq, const float* __restrict__ wk,
            const float* __restrict__ wv, const float* __restrict__ wo)
{
    const size_t i4 = (size_t)blockIdx.x * 256 + threadIdx.x;
    const size_t NT4 = (XN + 4 * WN) / 4;
    if (i4 >= NT4) return;
    const size_t e = i4 * 4;
    const float* src;
    uint32_t* dst;
    if (e < XN)               { src = x  + e;            dst = g_xt + e; }
    else if (e < XN + WN)     { src = wq + (e - XN);     dst = g_wt + (e - XN); }
    else if (e < XN + 2 * WN) { src = wk + (e - XN - WN);     dst = g_wt + WN     + (e - XN - WN); }
    else if (e < XN + 3 * WN) { src = wv + (e - XN - 2 * WN); dst = g_wt + 2 * WN + (e - XN - 2 * WN); }
    else                      { src = wo + (e - XN - 3 * WN); dst = g_wt + 3 * WN + (e - XN - 3 * WN); }
    float4 v = *(const float4*)src;
    uint4 o;
    o.x = f2tf32(v.x); o.y = f2tf32(v.y);
    o.z = f2tf32(v.z); o.w = f2tf32(v.w);
    *(uint4*)dst = o;
}

// ======================= tf32 mma.sync GEMM ================================
// 2-stage cp.async (R15 config) + explicit register double-buffered fragments.
#define GA_STRIDE 36
#define GB_STRIDE 136
#define GA_BYTES (128 * GA_STRIDE * 4)
#define GB_BYTES (32 * GB_STRIDE * 4)
#define GSTAGE   (GA_BYTES + GB_BYTES)
#define GA_OFF(s) ((s) * GSTAGE)
#define GB_OFF(s) ((s) * GSTAGE + GA_BYTES)
#define G_SMEM    (2 * GSTAGE)
#define G_NC      (D_ / 32)

template <int MODE>
__global__ void __launch_bounds__(256)
gemm_tc(const float* __restrict__ bias0,
        const float* __restrict__ bias1,
        const float* __restrict__ bias2,
        float* __restrict__ Cout)
{
    extern __shared__ char smc[];
    const uint32_t smb = smem_u32(smc);

    const uint32_t* W;
    const float* bias;
    uint32_t* dstq = nullptr;
    int zid = 0;
    if (MODE == 0) {
        zid = blockIdx.z;
        if (zid == 0)      { W = g_wt;          bias = bias0; dstq = g_q; }
        else if (zid == 1) { W = g_wt + WN;     bias = bias1; dstq = g_k; }
        else               { W = g_wt + 2 * WN; bias = bias2; dstq = g_v; }
    } else {
        W = g_wt + 3 * WN; bias = bias0;
    }
    const uint32_t* Ab = (MODE == 0) ? g_xt : g_attn;

    const int tid    = threadIdx.x;
    const int lid    = tid & 31;
    const int wid    = tid >> 5;
    const int warp_m = wid >> 2;
    const int warp_n = wid & 3;
    const int g      = lid >> 2;
    const int qq     = lid & 3;
    const int m0     = blockIdx.y * 128;
    const int n0     = blockIdx.x * 128;
    const int rb     = warp_m * 64;
    const int cb     = warp_n * 32;

    float acc[4][4][4];
#pragma unroll
    for (int mt = 0; mt < 4; mt++)
#pragma unroll
        for (int nt = 0; nt < 4; nt++)
#pragma unroll
            for (int e = 0; e < 4; e++) acc[mt][nt][e] = 0.f;

    auto load_chunk = [&](int c, int s) {
        const int k0 = c * 32;
        const uint32_t sa = smb + GA_OFF(s);
        const uint32_t sb = smb + GB_OFF(s);
#pragma unroll
        for (int i = 0; i < 4; i++) {
            const int e   = tid + i * 256;
            const int row = e >> 3;
            const int c4  = (e & 7) * 4;
            CP_ASYNC16(sa + (uint32_t)(row * GA_STRIDE + c4) * 4,
                       Ab + (size_t)(m0 + row) * D_ + k0 + c4);
        }
#pragma unroll
        for (int i = 0; i < 4; i++) {
            const int e  = tid + i * 256;
            const int kk = e >> 5;
            const int n4 = (e & 31) * 4;
            CP_ASYNC16(sb + (uint32_t)(kk * GB_STRIDE + n4) * 4,
                       W + (size_t)(k0 + kk) * D_ + n0 + n4);
        }
        CP_COMMIT();
    };

    load_chunk(0, 0);

#pragma unroll 1
    for (int c = 0; c < G_NC; c++) {
        const int s = c & 1;
        if (c + 1 < G_NC) {
            load_chunk(c + 1, s ^ 1);
            CP_WAIT1();
        } else {
            CP_WAIT0();
        }
        __syncthreads();

        const uint32_t (*As)[GA_STRIDE] = (const uint32_t(*)[GA_STRIDE])(smc + GA_OFF(s));
        const uint32_t (*Bs)[GB_STRIDE] = (const uint32_t(*)[GB_STRIDE])(smc + GB_OFF(s));

        // register double-buffered fragments: load k8+1 while k8's mmas run
        uint32_t bf[2][4][2];
        uint32_t af[2][4][4];
#pragma unroll
        for (int nt = 0; nt < 4; nt++) {
            bf[0][nt][0] = Bs[qq][cb + nt * 8 + g];
            bf[0][nt][1] = Bs[qq + 4][cb + nt * 8 + g];
        }
#pragma unroll
        for (int mt = 0; mt < 4; mt++) {
            const int r = rb + mt * 16 + g;
            af[0][mt][0] = As[r][qq];
            af[0][mt][1] = As[r + 8][qq];
            af[0][mt][2] = As[r][qq + 4];
            af[0][mt][3] = As[r + 8][qq + 4];
        }

#pragma unroll
        for (int k8 = 0; k8 < 4; k8++) {
            const int cur = k8 & 1;
            const int nxt = cur ^ 1;
            if (k8 + 1 < 4) {
                const int k0 = (k8 + 1) * 8;
#pragma unroll
                for (int nt = 0; nt < 4; nt++) {
                    bf[nxt][nt][0] = Bs[k0 + qq][cb + nt * 8 + g];
                    bf[nxt][nt][1] = Bs[k0 + qq + 4][cb + nt * 8 + g];
                }
#pragma unroll
                for (int mt = 0; mt < 4; mt++) {
                    const int r = rb + mt * 16 + g;
                    af[nxt][mt][0] = As[r][k0 + qq];
                    af[nxt][mt][1] = As[r + 8][k0 + qq];
                    af[nxt][mt][2] = As[r][k0 + qq + 4];
                    af[nxt][mt][3] = As[r + 8][k0 + qq + 4];
                }
            }
#pragma unroll
            for (int mt = 0; mt < 4; mt++)
#pragma unroll
                for (int nt = 0; nt < 4; nt++)
                    mma_tf32(acc[mt][nt],
                             af[cur][mt][0], af[cur][mt][1],
                             af[cur][mt][2], af[cur][mt][3],
                             bf[cur][nt][0], bf[cur][nt][1]);
        }
        __syncthreads();
    }

    // ---- epilogue ----
    const float qscale = (MODE == 0 && zid == 0) ? 0.125f : 1.f;
#pragma unroll
    for (int mt = 0; mt < 4; mt++) {
#pragma unroll
        for (int half = 0; half < 2; half++) {
            const int m  = m0 + rb + mt * 16 + half * 8 + g;
            const int bb = m / S_;
            const int ss = m % S_;
#pragma unroll
            for (int nt = 0; nt < 4; nt++) {
                const int gc = n0 + cb + nt * 8 + 2 * qq;
                float vx = acc[mt][nt][half * 2 + 0] + bias[gc];
                float vy = acc[mt][nt][half * 2 + 1] + bias[gc + 1];
                if (MODE == 0) {
                    const int h = gc >> 6;
                    const int d = gc & 63;
                    uint2 o = make_uint2(f2tf32(vx * qscale), f2tf32(vy * qscale));
                    *(uint2*)(dstq + ((((size_t)bb * H_ + h) * S_ + ss) << 6) + d) = o;
                } else {
                    *(float2*)(Cout + (size_t)m * D_ + gc) = make_float2(vx, vy);
                }
            }
        }
    }
}

// ======================= tf32 mma.sync flash attention (R16) ===============
#define AP_OFF 0                                  // [128][68]: Q staging, then P
#define AK_OFF(s) (128 * 68 + (s) * 64 * 68)
#define AV_OFF(s) (128 * 68 + 2 * 64 * 68 + (s) * 64 * 72)
#define A_SMEM_W  (128 * 68 + 2 * 64 * 68 + 2 * 64 * 72)   // 106496 B

__global__ void __launch_bounds__(256, 2)
attn_kernel()
{
    extern __shared__ uint32_t sm[];
    const uint32_t smb = smem_u32(sm);
    uint32_t* PS = sm + AP_OFF;

    const int qt  = (int)gridDim.x - 1 - (int)blockIdx.x;   // longest first
    const int bh  = blockIdx.y;
    const int b   = bh >> 4;
    const int h   = bh & 15;
    const int tid = threadIdx.x;
    const int lid = tid & 31;
    const int wid = tid >> 5;
    const int g   = lid >> 2;
    const int qq  = lid & 3;
    const int q0  = qt * 128;
    const int rw  = wid * 16 + g;

    const uint32_t* Qp = g_q + (size_t)bh * S_ * HD_;
    const uint32_t* Kp = g_k + (size_t)bh * S_ * HD_;
    const uint32_t* Vp = g_v + (size_t)bh * S_ * HD_;

    auto load_kv = [&](int t, int s) {
        const int k0 = t * 64;
        const uint32_t ks = smb + (AK_OFF(s)) * 4;
        const uint32_t vs = smb + (AV_OFF(s)) * 4;
#pragma unroll
        for (int i = 0; i < 4; i++) {
            const int e   = tid + i * 256;
            const int row = e >> 4;
            const int c4  = (e & 15) * 4;
            CP_ASYNC16(ks + (uint32_t)(row * 68 + c4) * 4,
                       Kp + (size_t)(k0 + row) * HD_ + c4);
            CP_ASYNC16(vs + (uint32_t)(row * 72 + c4) * 4,
                       Vp + (size_t)(k0 + row) * HD_ + c4);
        }
        CP_COMMIT();
    };

    load_kv(0, 0);

    // ---- stage Q through PS, pull fragments to registers ----
#pragma unroll
    for (int i = 0; i < 8; i++) {
        const int e   = tid + i * 256;
        const int row = e >> 4;
        const int c4  = (e & 15) * 4;
        uint4 qv = *(const uint4*)(Qp + (size_t)(q0 + row) * HD_ + c4);
        *(uint4*)(PS + row * 68 + c4) = qv;
    }
    __syncthreads();
    uint32_t qa[8][4];
#pragma unroll
    for (int kk = 0; kk < 8; kk++) {
        const int k = kk * 8 + qq;
        qa[kk][0] = PS[rw * 68 + k];
        qa[kk][1] = PS[(rw + 8) * 68 + k];
        qa[kk][2] = PS[rw * 68 + k + 4];
        qa[kk][3] = PS[(rw + 8) * 68 + k + 4];
    }
    __syncthreads();

    float m0 = -1e30f, m1 = -1e30f, l0 = 0.f, l1 = 0.f;
    float O[8][4];
#pragma unroll
    for (int nt = 0; nt < 8; nt++)
#pragma unroll
        for (int e = 0; e < 4; e++) O[nt][e] = 0.f;

    const int ntiles = 2 * qt + 2;   // causal
#pragma unroll 1
    for (int t = 0; t < ntiles; t++) {
        const int s = t & 1;
        if (t + 1 < ntiles) {
            load_kv(t + 1, s ^ 1);
            CP_WAIT1();
        } else {
            CP_WAIT0();
        }
        __syncthreads();

        const uint32_t (*KS)[68] = (const uint32_t(*)[68])(sm + AK_OFF(s));
        const uint32_t (*VS)[72] = (const uint32_t(*)[72])(sm + AV_OFF(s));

        float sc[8][4];
#pragma unroll
        for (int nt = 0; nt < 8; nt++)
#pragma unroll
            for (int e = 0; e < 4; e++) sc[nt][e] = 0.f;

#pragma unroll
        for (int kk = 0; kk < 8; kk++) {
            const int k = kk * 8 + qq;
#pragma unroll
            for (int nt = 0; nt < 8; nt++) {
                uint32_t b0 = KS[nt * 8 + g][k];
                uint32_t b1 = KS[nt * 8 + g][k + 4];
                mma_tf32(sc[nt], qa[kk][0], qa[kk][1], qa[kk][2], qa[kk][3],
                         b0, b1);
            }
        }

        const int k0g = t * 64;
        if (t + 2 >= ntiles) {
            const int qi0 = q0 + rw;
            const int qi1 = qi0 + 8;
#pragma unroll
            for (int nt = 0; nt < 8; nt++) {
                const int c0 = k0g + nt * 8 + 2 * qq;
                if (c0 > qi0)     sc[nt][0] = -1e30f;
                if (c0 + 1 > qi0) sc[nt][1] = -1e30f;
                if (c0 > qi1)     sc[nt][2] = -1e30f;
                if (c0 + 1 > qi1) sc[nt][3] = -1e30f;
            }
        }

        float mx0 = -1e30f, mx1 = -1e30f;
#pragma unroll
        for (int nt = 0; nt < 8; nt++) {
            mx0 = fmaxf(mx0, fmaxf(sc[nt][0], sc[nt][1]));
            mx1 = fmaxf(mx1, fmaxf(sc[nt][2], sc[nt][3]));
        }
        mx0 = fmaxf(mx0, __shfl_xor_sync(0xffffffffu, mx0, 1));
        mx0 = fmaxf(mx0, __shfl_xor_sync(0xffffffffu, mx0, 2));
        mx1 = fmaxf(mx1, __shfl_xor_sync(0xffffffffu, mx1, 1));
        mx1 = fmaxf(mx1, __shfl_xor_sync(0xffffffffu, mx1, 2));

        const float mn0 = fmaxf(m0, mx0);
        const float mn1 = fmaxf(m1, mx1);
        const float al0 = __expf(m0 - mn0);
        const float al1 = __expf(m1 - mn1);

        float ls0 = 0.f, ls1 = 0.f;
#pragma unroll
        for (int nt = 0; nt < 8; nt++) {
            float p00 = __expf(sc[nt][0] - mn0);
            float p01 = __expf(sc[nt][1] - mn0);
            float p10 = __expf(sc[nt][2] - mn1);
            float p11 = __expf(sc[nt][3] - mn1);
            ls0 += p00 + p01;
            ls1 += p10 + p11;
            *(uint2*)(PS + rw * 68 + nt * 8 + 2 * qq) =
                make_uint2(f2tf32(p00), f2tf32(p01));
            *(uint2*)(PS + (rw + 8) * 68 + nt * 8 + 2 * qq) =
                make_uint2(f2tf32(p10), f2tf32(p11));
        }
        ls0 += __shfl_xor_sync(0xffffffffu, ls0, 1);
        ls0 += __shfl_xor_sync(0xffffffffu, ls0, 2);
        ls1 += __shfl_xor_sync(0xffffffffu, ls1, 1);
        ls1 += __shfl_xor_sync(0xffffffffu, ls1, 2);
        l0 = l0 * al0 + ls0;
        l1 = l1 * al1 + ls1;
        m0 = mn0; m1 = mn1;
#pragma unroll
        for (int nt = 0; nt < 8; nt++) {
            O[nt][0] *= al0; O[nt][1] *= al0;
            O[nt][2] *= al1; O[nt][3] *= al1;
        }
        __syncwarp();

#pragma unroll
        for (int kk = 0; kk < 8; kk++) {
            const int k = kk * 8 + qq;
            uint32_t a0 = PS[rw * 68 + k];
            uint32_t a1 = PS[(rw + 8) * 68 + k];
            uint32_t a2 = PS[rw * 68 + k + 4];
            uint32_t a3 = PS[(rw + 8) * 68 + k + 4];
#pragma unroll
            for (int nt = 0; nt < 8; nt++) {
                uint32_t b0 = VS[kk * 8 + qq][nt * 8 + g];
                uint32_t b1 = VS[kk * 8 + qq + 4][nt * 8 + g];
                mma_tf32(O[nt], a0, a1, a2, a3, b0, b1);
            }
        }
        __syncthreads();
    }

    const float inv0 = 1.f / l0;
    const float inv1 = 1.f / l1;
    const int qg0 = q0 + rw;
    uint32_t* d0 = g_attn + ((size_t)(b * S_ + qg0)) * D_ + h * HD_;
    uint32_t* d1 = d0 + (size_t)8 * D_;
#pragma unroll
    for (int nt = 0; nt < 8; nt++) {
        const int col = nt * 8 + 2 * qq;
        *(uint2*)(d0 + col) =
            make_uint2(f2tf32(O[nt][0] * inv0), f2tf32(O[nt][1] * inv0));
        *(uint2*)(d1 + col) =
            make_uint2(f2tf32(O[nt][2] * inv1), f2tf32(O[nt][3] * inv1));
    }
}

// ---------------------------------------------------------------------------
extern "C" void kernel_launch(void* const* d_in, const int* in_sizes, int n_in,
                              void* d_out, int out_size)
{
    const float* x  = (const float*)d_in[0];
    const float* wq = (const float*)d_in[1];
    const float* bq = (const float*)d_in[2];
    const float* wk = (const float*)d_in[3];
    const float* bk = (const float*)d_in[4];
    const float* wv = (const float*)d_in[5];
    const float* bv = (const float*)d_in[6];
    const float* wo = (const float*)d_in[7];
    const float* bo = (const float*)d_in[8];
    float* out = (float*)d_out;

    cudaFuncSetAttribute(attn_kernel,
                         cudaFuncAttributeMaxDynamicSharedMemorySize,
                         A_SMEM_W * (int)sizeof(uint32_t));
    cudaFuncSetAttribute(gemm_tc<0>,
                         cudaFuncAttributeMaxDynamicSharedMemorySize, G_SMEM);
    cudaFuncSetAttribute(gemm_tc<1>,
                         cudaFuncAttributeMaxDynamicSharedMemorySize, G_SMEM);

    // 0) convert x + weights to tf32 bits
    const int prep_blocks = (int)(((XN + 4 * WN) / 4 + 255) / 256);
    prep_kernel<<<prep_blocks, 256>>>(x, wq, wk, wv, wo);

    // 1) fused QKV projections -> g_q/g_k/g_v (tf32 bits, [B,H,S,hd])
    dim3 gq(D_ / 128, M_ / 128, 3);
    gemm_tc<0><<<gq, 256, G_SMEM>>>(bq, bk, bv, nullptr);

    // 2) causal flash attention -> g_attn (tf32 bits, [B,S,D])
    dim3 ga(S_ / 128, B_ * H_);
    attn_kernel<<<ga, 256, A_SMEM_W * (int)sizeof(uint32_t)>>>();

    // 3) output projection -> d_out (fp32)
    dim3 go(D_ / 128, M_ / 128, 1);
    gemm_tc<1><<<go, 256, G_SMEM>>>(bo, nullptr, nullptr, out);
}